// round 1
// baseline (speedup 1.0000x reference)
#include <cuda_runtime.h>
#include <math.h>

// Problem constants
#define D_MODEL 1024
#define N_HEADS 16
#define HD      64
#define BATCH   4
#define SEQ     2048
#define BH      (BATCH * N_HEADS)   // 64
#define M_TOK   (BATCH * SEQ)       // 8192

// Scratch (device globals: allocation-free per harness rules)
__device__ float g_Q[(size_t)BH * SEQ * HD];
__device__ float g_K[(size_t)BH * SEQ * HD];
__device__ float g_V[(size_t)BH * SEQ * HD];
__device__ float g_Y[(size_t)M_TOK * D_MODEL];

// ---------------------------------------------------------------------------
// SGEMM: C[M,N] = A[M,K] @ B[K,N] + bias[N]
// 128x128 tile, BK=8, 256 threads, 8x8 per-thread microtile.
// MODE 0: A = g_Y (ignore A param), write C to param C (proj output).
// MODE 1: A = param A (x), scatter output into g_Q/g_K/g_V as [B,H,T,HD].
// ---------------------------------------------------------------------------
template <int MODE>
__global__ void __launch_bounds__(256, 2)
sgemm_kernel(const float* __restrict__ A, const float* __restrict__ B,
             const float* __restrict__ bias, float* __restrict__ C,
             int M, int N, int K)
{
    __shared__ float As[8][128];   // A tile transposed: [k][m]
    __shared__ float Bs[8][128];   // B tile: [k][n]

    const int tid = threadIdx.x;
    const int tx  = tid & 15;      // 0..15 -> n microtile
    const int ty  = tid >> 4;      // 0..15 -> m microtile
    const int m0  = blockIdx.y * 128;
    const int n0  = blockIdx.x * 128;

    const float* Ap = (MODE == 0) ? g_Y : A;

    float acc[8][8];
#pragma unroll
    for (int i = 0; i < 8; i++)
#pragma unroll
        for (int j = 0; j < 8; j++) acc[i][j] = 0.0f;

    const int arow = tid >> 1;           // 0..127
    const int acol = (tid & 1) * 4;      // 0 or 4
    const int brow = tid >> 5;           // 0..7
    const int bcol = (tid & 31) * 4;     // 0..124

    const float* Aptr = Ap + (size_t)(m0 + arow) * K + acol;
    const float* Bptr = B + (size_t)brow * N + n0 + bcol;

    for (int k0 = 0; k0 < K; k0 += 8) {
        float4 av = *(const float4*)(Aptr + k0);
        float4 bv = *(const float4*)(Bptr + (size_t)k0 * N);
        As[acol + 0][arow] = av.x;
        As[acol + 1][arow] = av.y;
        As[acol + 2][arow] = av.z;
        As[acol + 3][arow] = av.w;
        *(float4*)&Bs[brow][bcol] = bv;
        __syncthreads();

#pragma unroll
        for (int kk = 0; kk < 8; kk++) {
            float a[8], b[8];
            *(float4*)(a)     = *(const float4*)&As[kk][ty * 8];
            *(float4*)(a + 4) = *(const float4*)&As[kk][ty * 8 + 4];
            *(float4*)(b)     = *(const float4*)&Bs[kk][tx * 8];
            *(float4*)(b + 4) = *(const float4*)&Bs[kk][tx * 8 + 4];
#pragma unroll
            for (int i = 0; i < 8; i++)
#pragma unroll
                for (int j = 0; j < 8; j++)
                    acc[i][j] = fmaf(a[i], b[j], acc[i][j]);
        }
        __syncthreads();
    }

#pragma unroll
    for (int i = 0; i < 8; i++) {
        const int m = m0 + ty * 8 + i;
#pragma unroll
        for (int j = 0; j < 8; j++) {
            const int n = n0 + tx * 8 + j;
            const float c = acc[i][j] + bias[n];
            if (MODE == 0) {
                C[(size_t)m * N + n] = c;
            } else {
                const int which = n >> 10;        // 0=Q 1=K 2=V
                const int c2    = n & 1023;
                const int h     = c2 >> 6;
                const int d     = c2 & 63;
                const int bb    = m >> 11;        // batch
                const int t     = m & 2047;       // seq pos
                float* dst = (which == 0) ? g_Q : (which == 1) ? g_K : g_V;
                dst[(((size_t)(bb * N_HEADS + h)) * SEQ + t) * HD + d] = c;
            }
        }
    }
}

// ---------------------------------------------------------------------------
// Flash attention, causal. Per block: 64 queries of one (b,h).
// 256 threads = 16x16; thread (ty,tx) owns 4 q-rows x 4 cols.
// Smem exactly 48KB: Q^T [d][m], K^T [d][n] (reused for P [m][n]), V [n][d].
// ---------------------------------------------------------------------------
__global__ void __launch_bounds__(256, 3)
flash_kernel()
{
    __shared__ float Qst[64][64];   // Q^T
    __shared__ float KPs[64][64];   // K^T, then P
    __shared__ float Vs[64][64];    // V

    const int tid = threadIdx.x;
    const int tx  = tid & 15;
    const int ty  = tid >> 4;
    const int qt  = blockIdx.x;          // 0..31
    const int bh  = blockIdx.y;          // 0..63
    const int q0  = qt * 64;

    // Load Q tile transposed
    {
        const int m  = tid & 63;
        const int d0 = (tid >> 6) * 16;
        const float* src = g_Q + ((size_t)bh * SEQ + q0 + m) * HD + d0;
#pragma unroll
        for (int d = 0; d < 16; d += 4) {
            float4 v = *(const float4*)(src + d);
            Qst[d0 + d + 0][m] = v.x;
            Qst[d0 + d + 1][m] = v.y;
            Qst[d0 + d + 2][m] = v.z;
            Qst[d0 + d + 3][m] = v.w;
        }
    }

    float mi[4], li[4], O[4][4];
#pragma unroll
    for (int i = 0; i < 4; i++) {
        mi[i] = -1e30f;
        li[i] = 0.0f;
#pragma unroll
        for (int j = 0; j < 4; j++) O[i][j] = 0.0f;
    }

    const float SCALE = 0.125f;  // 1/sqrt(64)

    for (int kt = 0; kt <= qt; kt++) {
        const int n0 = kt * 64;
        __syncthreads();  // prior PV reads of KPs/Vs complete (also covers Q load)

        // Load K^T tile
        {
            const int n  = tid & 63;
            const int d0 = (tid >> 6) * 16;
            const float* ksrc = g_K + ((size_t)bh * SEQ + n0 + n) * HD + d0;
#pragma unroll
            for (int d = 0; d < 16; d += 4) {
                float4 v = *(const float4*)(ksrc + d);
                KPs[d0 + d + 0][n] = v.x;
                KPs[d0 + d + 1][n] = v.y;
                KPs[d0 + d + 2][n] = v.z;
                KPs[d0 + d + 3][n] = v.w;
            }
        }
        // Load V tile (coalesced)
        {
            const int nv = tid >> 2;
            const int dv = (tid & 3) * 16;
            const float* vsrc = g_V + ((size_t)bh * SEQ + n0 + nv) * HD + dv;
#pragma unroll
            for (int d = 0; d < 16; d += 4)
                *(float4*)&Vs[nv][dv + d] = *(const float4*)(vsrc + d);
        }
        __syncthreads();

        // S = Q K^T
        float s[4][4];
#pragma unroll
        for (int i = 0; i < 4; i++)
#pragma unroll
            for (int j = 0; j < 4; j++) s[i][j] = 0.0f;

#pragma unroll 8
        for (int k = 0; k < 64; k++) {
            float4 q  = *(const float4*)&Qst[k][ty * 4];
            float4 kv = *(const float4*)&KPs[k][tx * 4];
            const float qa[4] = {q.x, q.y, q.z, q.w};
            const float kb[4] = {kv.x, kv.y, kv.z, kv.w};
#pragma unroll
            for (int i = 0; i < 4; i++)
#pragma unroll
                for (int j = 0; j < 4; j++)
                    s[i][j] = fmaf(qa[i], kb[j], s[i][j]);
        }

        // Scale + causal mask (only diagonal tile)
#pragma unroll
        for (int i = 0; i < 4; i++)
#pragma unroll
            for (int j = 0; j < 4; j++) {
                s[i][j] *= SCALE;
                if (kt == qt && (tx * 4 + j) > (ty * 4 + i)) s[i][j] = -1e30f;
            }

        // Online softmax (row groups of 16 lanes, xor-shuffle reduce)
        float alpha[4];
#pragma unroll
        for (int i = 0; i < 4; i++) {
            float rm = fmaxf(fmaxf(s[i][0], s[i][1]), fmaxf(s[i][2], s[i][3]));
#pragma unroll
            for (int off = 8; off >= 1; off >>= 1)
                rm = fmaxf(rm, __shfl_xor_sync(0xffffffffu, rm, off));
            const float new_m = fmaxf(mi[i], rm);
            alpha[i] = __expf(mi[i] - new_m);
            mi[i] = new_m;
            float rs = 0.0f;
#pragma unroll
            for (int j = 0; j < 4; j++) {
                s[i][j] = __expf(s[i][j] - new_m);
                rs += s[i][j];
            }
#pragma unroll
            for (int off = 8; off >= 1; off >>= 1)
                rs += __shfl_xor_sync(0xffffffffu, rs, off);
            li[i] = li[i] * alpha[i] + rs;
#pragma unroll
            for (int j = 0; j < 4; j++) O[i][j] *= alpha[i];
        }

        __syncthreads();  // all reads of K^T done before P overwrites it

        // Store P into KPs as [m][n]
#pragma unroll
        for (int i = 0; i < 4; i++)
            *(float4*)&KPs[ty * 4 + i][tx * 4] =
                make_float4(s[i][0], s[i][1], s[i][2], s[i][3]);
        __syncthreads();

        // O += P V
#pragma unroll 8
        for (int n = 0; n < 64; n++) {
            float4 v = *(const float4*)&Vs[n][tx * 4];
            const float vb[4] = {v.x, v.y, v.z, v.w};
            float p[4];
#pragma unroll
            for (int i = 0; i < 4; i++) p[i] = KPs[ty * 4 + i][n];
#pragma unroll
            for (int i = 0; i < 4; i++)
#pragma unroll
                for (int j = 0; j < 4; j++)
                    O[i][j] = fmaf(p[i], vb[j], O[i][j]);
        }
    }

    // Normalize and write Y[b, t, h*64 + d]
    const int b = bh >> 4;
    const int h = bh & 15;
#pragma unroll
    for (int i = 0; i < 4; i++) {
        const float inv = 1.0f / li[i];
        const int t = q0 + ty * 4 + i;
        float4 o = make_float4(O[i][0] * inv, O[i][1] * inv,
                               O[i][2] * inv, O[i][3] * inv);
        *(float4*)&g_Y[((size_t)b * SEQ + t) * D_MODEL + h * 64 + tx * 4] = o;
    }
}

// ---------------------------------------------------------------------------
extern "C" void kernel_launch(void* const* d_in, const int* in_sizes, int n_in,
                              void* d_out, int out_size)
{
    const float* x      = (const float*)d_in[0];  // [4,2048,1024]
    const float* W_attn = (const float*)d_in[1];  // [1024,3072]
    const float* b_attn = (const float*)d_in[2];  // [3072]
    const float* W_proj = (const float*)d_in[3];  // [1024,1024]
    const float* b_proj = (const float*)d_in[4];  // [1024]
    float* out = (float*)d_out;                   // [4,2048,1024]

    // 1) QKV projection, scatter into g_Q/g_K/g_V
    {
        dim3 grid(3 * D_MODEL / 128, M_TOK / 128);  // (24, 64)
        sgemm_kernel<1><<<grid, 256>>>(x, W_attn, b_attn, nullptr,
                                       M_TOK, 3 * D_MODEL, D_MODEL);
    }
    // 2) Causal flash attention -> g_Y
    {
        dim3 grid(SEQ / 64, BH);  // (32, 64)
        flash_kernel<<<grid, 256>>>();
    }
    // 3) Output projection -> d_out
    {
        dim3 grid(D_MODEL / 128, M_TOK / 128);  // (8, 64)
        sgemm_kernel<0><<<grid, 256>>>(nullptr, W_proj, b_proj, out,
                                       M_TOK, D_MODEL, D_MODEL);
    }
}

// round 4
// speedup vs baseline: 1.6234x; 1.6234x over previous
#include <cuda_runtime.h>
#include <math.h>
#include <stdint.h>

// Problem constants
#define D_MODEL 1024
#define N_HEADS 16
#define HD      64
#define BATCH   4
#define SEQ     2048
#define BH      (BATCH * N_HEADS)   // 64
#define M_TOK   (BATCH * SEQ)       // 8192

// Scratch (device globals: allocation-free per harness rules)
__device__ float g_Q[(size_t)BH * SEQ * HD];
__device__ float g_K[(size_t)BH * SEQ * HD];
__device__ float g_V[(size_t)BH * SEQ * HD];
__device__ float g_Y[(size_t)M_TOK * D_MODEL];
__device__ float g_WTa[(size_t)3 * D_MODEL * D_MODEL];  // W_attn^T [3072][1024]
__device__ float g_WTp[(size_t)D_MODEL * D_MODEL];      // W_proj^T [1024][1024]

// ---------------------------------------------------------------------------
// mma.sync tf32 helpers (base-target ISA; sm_80+)
// ---------------------------------------------------------------------------
__device__ __forceinline__ uint32_t f2tf32(float f) {
    uint32_t r;
    asm("cvt.rna.tf32.f32 %0, %1;" : "=r"(r) : "f"(f));
    return r;
}
__device__ __forceinline__ void mma_tf32(float d[4], const uint32_t a[4],
                                         const uint32_t b[2]) {
    asm volatile(
        "mma.sync.aligned.m16n8k8.row.col.f32.tf32.tf32.f32 "
        "{%0,%1,%2,%3}, {%4,%5,%6,%7}, {%8,%9}, {%0,%1,%2,%3};"
        : "+f"(d[0]), "+f"(d[1]), "+f"(d[2]), "+f"(d[3])
        : "r"(a[0]), "r"(a[1]), "r"(a[2]), "r"(a[3]), "r"(b[0]), "r"(b[1]));
}

// ---------------------------------------------------------------------------
// Weight transpose: W[R][C] -> WT[C][R]
// ---------------------------------------------------------------------------
__global__ void transpose_kernel(const float* __restrict__ W, float* __restrict__ WT,
                                 int R, int C)
{
    __shared__ float t[32][33];
    const int c0 = blockIdx.x * 32, r0 = blockIdx.y * 32;
    const int tx = threadIdx.x, ty = threadIdx.y;  // 32x8
#pragma unroll
    for (int i = 0; i < 32; i += 8)
        t[ty + i][tx] = W[(size_t)(r0 + ty + i) * C + c0 + tx];
    __syncthreads();
#pragma unroll
    for (int i = 0; i < 32; i += 8)
        WT[(size_t)(c0 + ty + i) * R + r0 + tx] = t[tx][ty + i];
}

// ---------------------------------------------------------------------------
// TF32 tensor-core GEMM via mma.sync: C = A[M,K] @ Bt[N,K]^T + bias.
// 128x128 CTA tile, BK=32, 8 warps (4 along M, 2 along N), warp tile 32x64.
// Smem tiles stored [row][36] (pad 36: float4-aligned STS, conflict-free LDS).
// MODE 1: A = x param, epilogue scatters into g_Q/g_K/g_V head-major.
// MODE 0: A = g_Y, epilogue writes Cout + bias.
// ---------------------------------------------------------------------------
#define LDW 36
#define TILE_U32 (128 * LDW)          // u32 elements per operand tile
#define BUF_BYTES (2 * TILE_U32 * 4)  // A+B one stage = 36864B

template <int MODE>
__global__ void __launch_bounds__(256)
gemm_mma(const float* __restrict__ Ain, const float* __restrict__ Bt,
         const float* __restrict__ bias, float* __restrict__ Cout)
{
    constexpr int K  = D_MODEL;   // 1024
    constexpr int NS = K / 32;    // 32 slabs

    const int tid  = threadIdx.x;
    const int wid  = tid >> 5;
    const int lane = tid & 31;
    const int g    = lane >> 2;   // 0..7
    const int tig  = lane & 3;    // 0..3
    const int m0   = blockIdx.y * 128;
    const int n0   = blockIdx.x * 128;
    const int wm   = (wid & 3) * 32;   // warp M offset in tile
    const int wn   = (wid >> 2) * 64;  // warp N offset in tile
    const float* A = (MODE == 0) ? g_Y : Ain;

    extern __shared__ uint32_t sm[];   // [2 stages][A tile | B tile]

    float acc[2][8][4];
#pragma unroll
    for (int mf = 0; mf < 2; mf++)
#pragma unroll
        for (int nf = 0; nf < 8; nf++)
#pragma unroll
            for (int r = 0; r < 4; r++) acc[mf][nf][r] = 0.0f;

    // Staging map: 4 float4 per operand per thread per slab.
    // f4idx = tid + 256*i: row = f4idx>>3 (0..127), c4 = f4idx&7 (col = c4*4)
    const float4* Ap[4];
    const float4* Bp[4];
    uint32_t soff[4];
#pragma unroll
    for (int i = 0; i < 4; i++) {
        const int idx = tid + 256 * i;
        const int row = idx >> 3, c4 = idx & 7;
        Ap[i] = (const float4*)(A  + (size_t)(m0 + row) * K + c4 * 4);
        Bp[i] = (const float4*)(Bt + (size_t)(n0 + row) * K + c4 * 4);
        soff[i] = row * LDW + c4 * 4;   // u32 index, 16B-aligned (LDW*4%16==0)
    }

    float4 ra[4], rb[4];
#pragma unroll
    for (int i = 0; i < 4; i++) { ra[i] = Ap[i][0]; rb[i] = Bp[i][0]; }
#pragma unroll
    for (int i = 0; i < 4; i++) {
        uint4 av = make_uint4(f2tf32(ra[i].x), f2tf32(ra[i].y),
                              f2tf32(ra[i].z), f2tf32(ra[i].w));
        uint4 bv = make_uint4(f2tf32(rb[i].x), f2tf32(rb[i].y),
                              f2tf32(rb[i].z), f2tf32(rb[i].w));
        *(uint4*)&sm[soff[i]]            = av;
        *(uint4*)&sm[TILE_U32 + soff[i]] = bv;
    }
    __syncthreads();

    for (int s = 0; s < NS; s++) {
        // Prefetch next slab into registers (8 float4 per operand-pair)
        if (s + 1 < NS) {
#pragma unroll
            for (int i = 0; i < 4; i++) {
                ra[i] = Ap[i][(s + 1) * 8];
                rb[i] = Bp[i][(s + 1) * 8];
            }
        }

        // Compute slab s from stage s&1
        const uint32_t* As = sm + (uint32_t)(s & 1) * (2 * TILE_U32);
        const uint32_t* Bs = As + TILE_U32;
#pragma unroll
        for (int ks = 0; ks < 4; ks++) {
            const int kb = ks * 8;
            uint32_t afr[2][4];
#pragma unroll
            for (int mf = 0; mf < 2; mf++) {
                const int r0i = wm + mf * 16 + g;
                afr[mf][0] = As[r0i * LDW + kb + tig];
                afr[mf][1] = As[(r0i + 8) * LDW + kb + tig];
                afr[mf][2] = As[r0i * LDW + kb + tig + 4];
                afr[mf][3] = As[(r0i + 8) * LDW + kb + tig + 4];
            }
            uint32_t bfr[8][2];
#pragma unroll
            for (int nf = 0; nf < 8; nf++) {
                const int nr = wn + nf * 8 + g;
                bfr[nf][0] = Bs[nr * LDW + kb + tig];
                bfr[nf][1] = Bs[nr * LDW + kb + tig + 4];
            }
#pragma unroll
            for (int mf = 0; mf < 2; mf++)
#pragma unroll
                for (int nf = 0; nf < 8; nf++)
                    mma_tf32(acc[mf][nf], afr[mf], bfr[nf]);
        }

        // Stage next slab into the other buffer
        if (s + 1 < NS) {
            __syncthreads();
            uint32_t* dst = sm + (uint32_t)((s + 1) & 1) * (2 * TILE_U32);
#pragma unroll
            for (int i = 0; i < 4; i++) {
                uint4 av = make_uint4(f2tf32(ra[i].x), f2tf32(ra[i].y),
                                      f2tf32(ra[i].z), f2tf32(ra[i].w));
                uint4 bv = make_uint4(f2tf32(rb[i].x), f2tf32(rb[i].y),
                                      f2tf32(rb[i].z), f2tf32(rb[i].w));
                *(uint4*)&dst[soff[i]]            = av;
                *(uint4*)&dst[TILE_U32 + soff[i]] = bv;
            }
            __syncthreads();
        }
    }

    // Epilogue. Fragment (mf,nf): rows m0+wm+mf*16+g (+8), cols n0+wn+nf*8+2*tig (+1)
#pragma unroll
    for (int mf = 0; mf < 2; mf++) {
        const int row0 = m0 + wm + mf * 16 + g;
#pragma unroll
        for (int nf = 0; nf < 8; nf++) {
            const int col = n0 + wn + nf * 8 + 2 * tig;
            const float2 bv = *(const float2*)(bias + col);
            float2 v0 = make_float2(acc[mf][nf][0] + bv.x, acc[mf][nf][1] + bv.y);
            float2 v1 = make_float2(acc[mf][nf][2] + bv.x, acc[mf][nf][3] + bv.y);
            if (MODE == 0) {
                *(float2*)(Cout + (size_t)row0 * D_MODEL + col)       = v0;
                *(float2*)(Cout + (size_t)(row0 + 8) * D_MODEL + col) = v1;
            } else {
                const int which = col >> 10;       // 0=Q 1=K 2=V
                const int c2    = col & 1023;
                const int h     = c2 >> 6;
                const int d     = c2 & 63;
                float* dst = (which == 0) ? g_Q : (which == 1) ? g_K : g_V;
                const int bb0 = row0 >> 11, t0 = row0 & 2047;
                const int r1  = row0 + 8;
                const int bb1 = r1 >> 11,   t1 = r1 & 2047;
                *(float2*)(dst + (((size_t)(bb0 * N_HEADS + h)) * SEQ + t0) * HD + d) = v0;
                *(float2*)(dst + (((size_t)(bb1 * N_HEADS + h)) * SEQ + t1) * HD + d) = v1;
            }
        }
    }
}

// ---------------------------------------------------------------------------
// Flash attention, causal (unchanged FFMA version).
// ---------------------------------------------------------------------------
__global__ void __launch_bounds__(256, 3)
flash_kernel()
{
    __shared__ float Qst[64][64];
    __shared__ float KPs[64][64];
    __shared__ float Vs[64][64];

    const int tid = threadIdx.x;
    const int tx  = tid & 15;
    const int ty  = tid >> 4;
    const int qt  = blockIdx.x;
    const int bh  = blockIdx.y;
    const int q0  = qt * 64;

    {
        const int m  = tid & 63;
        const int d0 = (tid >> 6) * 16;
        const float* src = g_Q + ((size_t)bh * SEQ + q0 + m) * HD + d0;
#pragma unroll
        for (int d = 0; d < 16; d += 4) {
            float4 v = *(const float4*)(src + d);
            Qst[d0 + d + 0][m] = v.x;
            Qst[d0 + d + 1][m] = v.y;
            Qst[d0 + d + 2][m] = v.z;
            Qst[d0 + d + 3][m] = v.w;
        }
    }

    float mi[4], li[4], O[4][4];
#pragma unroll
    for (int i = 0; i < 4; i++) {
        mi[i] = -1e30f;
        li[i] = 0.0f;
#pragma unroll
        for (int j = 0; j < 4; j++) O[i][j] = 0.0f;
    }

    const float SCALE = 0.125f;

    for (int kt = 0; kt <= qt; kt++) {
        const int n0 = kt * 64;
        __syncthreads();

        {
            const int n  = tid & 63;
            const int d0 = (tid >> 6) * 16;
            const float* ksrc = g_K + ((size_t)bh * SEQ + n0 + n) * HD + d0;
#pragma unroll
            for (int d = 0; d < 16; d += 4) {
                float4 v = *(const float4*)(ksrc + d);
                KPs[d0 + d + 0][n] = v.x;
                KPs[d0 + d + 1][n] = v.y;
                KPs[d0 + d + 2][n] = v.z;
                KPs[d0 + d + 3][n] = v.w;
            }
        }
        {
            const int nv = tid >> 2;
            const int dv = (tid & 3) * 16;
            const float* vsrc = g_V + ((size_t)bh * SEQ + n0 + nv) * HD + dv;
#pragma unroll
            for (int d = 0; d < 16; d += 4)
                *(float4*)&Vs[nv][dv + d] = *(const float4*)(vsrc + d);
        }
        __syncthreads();

        float s[4][4];
#pragma unroll
        for (int i = 0; i < 4; i++)
#pragma unroll
            for (int j = 0; j < 4; j++) s[i][j] = 0.0f;

#pragma unroll 8
        for (int k = 0; k < 64; k++) {
            float4 q  = *(const float4*)&Qst[k][ty * 4];
            float4 kv = *(const float4*)&KPs[k][tx * 4];
            const float qa[4] = {q.x, q.y, q.z, q.w};
            const float kb[4] = {kv.x, kv.y, kv.z, kv.w};
#pragma unroll
            for (int i = 0; i < 4; i++)
#pragma unroll
                for (int j = 0; j < 4; j++)
                    s[i][j] = fmaf(qa[i], kb[j], s[i][j]);
        }

#pragma unroll
        for (int i = 0; i < 4; i++)
#pragma unroll
            for (int j = 0; j < 4; j++) {
                s[i][j] *= SCALE;
                if (kt == qt && (tx * 4 + j) > (ty * 4 + i)) s[i][j] = -1e30f;
            }

        float alpha[4];
#pragma unroll
        for (int i = 0; i < 4; i++) {
            float rm = fmaxf(fmaxf(s[i][0], s[i][1]), fmaxf(s[i][2], s[i][3]));
#pragma unroll
            for (int off = 8; off >= 1; off >>= 1)
                rm = fmaxf(rm, __shfl_xor_sync(0xffffffffu, rm, off));
            const float new_m = fmaxf(mi[i], rm);
            alpha[i] = __expf(mi[i] - new_m);
            mi[i] = new_m;
            float rs = 0.0f;
#pragma unroll
            for (int j = 0; j < 4; j++) {
                s[i][j] = __expf(s[i][j] - new_m);
                rs += s[i][j];
            }
#pragma unroll
            for (int off = 8; off >= 1; off >>= 1)
                rs += __shfl_xor_sync(0xffffffffu, rs, off);
            li[i] = li[i] * alpha[i] + rs;
#pragma unroll
            for (int j = 0; j < 4; j++) O[i][j] *= alpha[i];
        }

        __syncthreads();

#pragma unroll
        for (int i = 0; i < 4; i++)
            *(float4*)&KPs[ty * 4 + i][tx * 4] =
                make_float4(s[i][0], s[i][1], s[i][2], s[i][3]);
        __syncthreads();

#pragma unroll 8
        for (int n = 0; n < 64; n++) {
            float4 v = *(const float4*)&Vs[n][tx * 4];
            const float vb[4] = {v.x, v.y, v.z, v.w};
            float p[4];
#pragma unroll
            for (int i = 0; i < 4; i++) p[i] = KPs[ty * 4 + i][n];
#pragma unroll
            for (int i = 0; i < 4; i++)
#pragma unroll
                for (int j = 0; j < 4; j++)
                    O[i][j] = fmaf(p[i], vb[j], O[i][j]);
        }
    }

    const int b = bh >> 4;
    const int h = bh & 15;
#pragma unroll
    for (int i = 0; i < 4; i++) {
        const float inv = 1.0f / li[i];
        const int t = q0 + ty * 4 + i;
        float4 o = make_float4(O[i][0] * inv, O[i][1] * inv,
                               O[i][2] * inv, O[i][3] * inv);
        *(float4*)&g_Y[((size_t)b * SEQ + t) * D_MODEL + h * 64 + tx * 4] = o;
    }
}

// ---------------------------------------------------------------------------
extern "C" void kernel_launch(void* const* d_in, const int* in_sizes, int n_in,
                              void* d_out, int out_size)
{
    const float* x      = (const float*)d_in[0];
    const float* W_attn = (const float*)d_in[1];
    const float* b_attn = (const float*)d_in[2];
    const float* W_proj = (const float*)d_in[3];
    const float* b_proj = (const float*)d_in[4];
    float* out = (float*)d_out;

    const int SMEM_BYTES = 2 * BUF_BYTES;  // 73728
    cudaFuncSetAttribute(gemm_mma<1>, cudaFuncAttributeMaxDynamicSharedMemorySize, SMEM_BYTES);
    cudaFuncSetAttribute(gemm_mma<0>, cudaFuncAttributeMaxDynamicSharedMemorySize, SMEM_BYTES);

    float* wta; cudaGetSymbolAddress((void**)&wta, g_WTa);
    float* wtp; cudaGetSymbolAddress((void**)&wtp, g_WTp);

    // 0) Transpose weights to K-major [n][k]
    {
        dim3 blk(32, 8);
        transpose_kernel<<<dim3(3 * D_MODEL / 32, D_MODEL / 32), blk>>>(W_attn, wta, D_MODEL, 3 * D_MODEL);
        transpose_kernel<<<dim3(D_MODEL / 32, D_MODEL / 32), blk>>>(W_proj, wtp, D_MODEL, D_MODEL);
    }
    // 1) QKV projection (tf32 mma.sync) -> g_Q/g_K/g_V
    {
        dim3 grid(3 * D_MODEL / 128, M_TOK / 128);  // (24, 64)
        gemm_mma<1><<<grid, 256, SMEM_BYTES>>>(x, wta, b_attn, nullptr);
    }
    // 2) Causal flash attention -> g_Y
    {
        dim3 grid(SEQ / 64, BH);
        flash_kernel<<<grid, 256>>>();
    }
    // 3) Output projection (tf32 mma.sync) -> d_out
    {
        dim3 grid(D_MODEL / 128, M_TOK / 128);  // (8, 64)
        gemm_mma<0><<<grid, 256, SMEM_BYTES>>>(nullptr, wtp, b_proj, out);
    }
}

// round 5
// speedup vs baseline: 2.8300x; 1.7433x over previous
#include <cuda_runtime.h>
#include <math.h>
#include <stdint.h>

// Problem constants
#define D_MODEL 1024
#define N_HEADS 16
#define HD      64
#define BATCH   4
#define SEQ     2048
#define BH      (BATCH * N_HEADS)   // 64
#define M_TOK   (BATCH * SEQ)       // 8192

// Scratch (device globals: allocation-free per harness rules)
__device__ float g_Q[(size_t)BH * SEQ * HD];
__device__ float g_K[(size_t)BH * SEQ * HD];
__device__ float g_V[(size_t)BH * SEQ * HD];
__device__ float g_Y[(size_t)M_TOK * D_MODEL];
__device__ float g_WTa[(size_t)3 * D_MODEL * D_MODEL];  // W_attn^T [3072][1024]
__device__ float g_WTp[(size_t)D_MODEL * D_MODEL];      // W_proj^T [1024][1024]

// ---------------------------------------------------------------------------
// mma.sync tf32 helpers (base-target ISA; sm_80+)
// ---------------------------------------------------------------------------
__device__ __forceinline__ uint32_t f2tf32(float f) {
    uint32_t r;
    asm("cvt.rna.tf32.f32 %0, %1;" : "=r"(r) : "f"(f));
    return r;
}
__device__ __forceinline__ void mma_tf32(float d[4], const uint32_t a[4],
                                         const uint32_t b[2]) {
    asm volatile(
        "mma.sync.aligned.m16n8k8.row.col.f32.tf32.tf32.f32 "
        "{%0,%1,%2,%3}, {%4,%5,%6,%7}, {%8,%9}, {%0,%1,%2,%3};"
        : "+f"(d[0]), "+f"(d[1]), "+f"(d[2]), "+f"(d[3])
        : "r"(a[0]), "r"(a[1]), "r"(a[2]), "r"(a[3]), "r"(b[0]), "r"(b[1]));
}

// ---------------------------------------------------------------------------
// Weight transpose: W[R][C] -> WT[C][R]
// ---------------------------------------------------------------------------
__global__ void transpose_kernel(const float* __restrict__ W, float* __restrict__ WT,
                                 int R, int C)
{
    __shared__ float t[32][33];
    const int c0 = blockIdx.x * 32, r0 = blockIdx.y * 32;
    const int tx = threadIdx.x, ty = threadIdx.y;  // 32x8
#pragma unroll
    for (int i = 0; i < 32; i += 8)
        t[ty + i][tx] = W[(size_t)(r0 + ty + i) * C + c0 + tx];
    __syncthreads();
#pragma unroll
    for (int i = 0; i < 32; i += 8)
        WT[(size_t)(c0 + ty + i) * R + r0 + tx] = t[tx][ty + i];
}

// ---------------------------------------------------------------------------
// TF32 tensor-core GEMM via mma.sync (unchanged from Round 4).
// ---------------------------------------------------------------------------
#define LDW 36
#define TILE_U32 (128 * LDW)
#define BUF_BYTES (2 * TILE_U32 * 4)

template <int MODE>
__global__ void __launch_bounds__(256)
gemm_mma(const float* __restrict__ Ain, const float* __restrict__ Bt,
         const float* __restrict__ bias, float* __restrict__ Cout)
{
    constexpr int K  = D_MODEL;
    constexpr int NS = K / 32;

    const int tid  = threadIdx.x;
    const int wid  = tid >> 5;
    const int lane = tid & 31;
    const int g    = lane >> 2;
    const int tig  = lane & 3;
    const int m0   = blockIdx.y * 128;
    const int n0   = blockIdx.x * 128;
    const int wm   = (wid & 3) * 32;
    const int wn   = (wid >> 2) * 64;
    const float* A = (MODE == 0) ? g_Y : Ain;

    extern __shared__ uint32_t sm[];

    float acc[2][8][4];
#pragma unroll
    for (int mf = 0; mf < 2; mf++)
#pragma unroll
        for (int nf = 0; nf < 8; nf++)
#pragma unroll
            for (int r = 0; r < 4; r++) acc[mf][nf][r] = 0.0f;

    const float4* Ap[4];
    const float4* Bp[4];
    uint32_t soff[4];
#pragma unroll
    for (int i = 0; i < 4; i++) {
        const int idx = tid + 256 * i;
        const int row = idx >> 3, c4 = idx & 7;
        Ap[i] = (const float4*)(A  + (size_t)(m0 + row) * K + c4 * 4);
        Bp[i] = (const float4*)(Bt + (size_t)(n0 + row) * K + c4 * 4);
        soff[i] = row * LDW + c4 * 4;
    }

    float4 ra[4], rb[4];
#pragma unroll
    for (int i = 0; i < 4; i++) { ra[i] = Ap[i][0]; rb[i] = Bp[i][0]; }
#pragma unroll
    for (int i = 0; i < 4; i++) {
        uint4 av = make_uint4(f2tf32(ra[i].x), f2tf32(ra[i].y),
                              f2tf32(ra[i].z), f2tf32(ra[i].w));
        uint4 bv = make_uint4(f2tf32(rb[i].x), f2tf32(rb[i].y),
                              f2tf32(rb[i].z), f2tf32(rb[i].w));
        *(uint4*)&sm[soff[i]]            = av;
        *(uint4*)&sm[TILE_U32 + soff[i]] = bv;
    }
    __syncthreads();

    for (int s = 0; s < NS; s++) {
        if (s + 1 < NS) {
#pragma unroll
            for (int i = 0; i < 4; i++) {
                ra[i] = Ap[i][(s + 1) * 8];
                rb[i] = Bp[i][(s + 1) * 8];
            }
        }

        const uint32_t* As = sm + (uint32_t)(s & 1) * (2 * TILE_U32);
        const uint32_t* Bs = As + TILE_U32;
#pragma unroll
        for (int ks = 0; ks < 4; ks++) {
            const int kb = ks * 8;
            uint32_t afr[2][4];
#pragma unroll
            for (int mf = 0; mf < 2; mf++) {
                const int r0i = wm + mf * 16 + g;
                afr[mf][0] = As[r0i * LDW + kb + tig];
                afr[mf][1] = As[(r0i + 8) * LDW + kb + tig];
                afr[mf][2] = As[r0i * LDW + kb + tig + 4];
                afr[mf][3] = As[(r0i + 8) * LDW + kb + tig + 4];
            }
            uint32_t bfr[8][2];
#pragma unroll
            for (int nf = 0; nf < 8; nf++) {
                const int nr = wn + nf * 8 + g;
                bfr[nf][0] = Bs[nr * LDW + kb + tig];
                bfr[nf][1] = Bs[nr * LDW + kb + tig + 4];
            }
#pragma unroll
            for (int mf = 0; mf < 2; mf++)
#pragma unroll
                for (int nf = 0; nf < 8; nf++)
                    mma_tf32(acc[mf][nf], afr[mf], bfr[nf]);
        }

        if (s + 1 < NS) {
            __syncthreads();
            uint32_t* dst = sm + (uint32_t)((s + 1) & 1) * (2 * TILE_U32);
#pragma unroll
            for (int i = 0; i < 4; i++) {
                uint4 av = make_uint4(f2tf32(ra[i].x), f2tf32(ra[i].y),
                                      f2tf32(ra[i].z), f2tf32(ra[i].w));
                uint4 bv = make_uint4(f2tf32(rb[i].x), f2tf32(rb[i].y),
                                      f2tf32(rb[i].z), f2tf32(rb[i].w));
                *(uint4*)&dst[soff[i]]            = av;
                *(uint4*)&dst[TILE_U32 + soff[i]] = bv;
            }
            __syncthreads();
        }
    }

#pragma unroll
    for (int mf = 0; mf < 2; mf++) {
        const int row0 = m0 + wm + mf * 16 + g;
#pragma unroll
        for (int nf = 0; nf < 8; nf++) {
            const int col = n0 + wn + nf * 8 + 2 * tig;
            const float2 bv = *(const float2*)(bias + col);
            float2 v0 = make_float2(acc[mf][nf][0] + bv.x, acc[mf][nf][1] + bv.y);
            float2 v1 = make_float2(acc[mf][nf][2] + bv.x, acc[mf][nf][3] + bv.y);
            if (MODE == 0) {
                *(float2*)(Cout + (size_t)row0 * D_MODEL + col)       = v0;
                *(float2*)(Cout + (size_t)(row0 + 8) * D_MODEL + col) = v1;
            } else {
                const int which = col >> 10;
                const int c2    = col & 1023;
                const int h     = c2 >> 6;
                const int d     = c2 & 63;
                float* dst = (which == 0) ? g_Q : (which == 1) ? g_K : g_V;
                const int bb0 = row0 >> 11, t0 = row0 & 2047;
                const int r1  = row0 + 8;
                const int bb1 = r1 >> 11,   t1 = r1 & 2047;
                *(float2*)(dst + (((size_t)(bb0 * N_HEADS + h)) * SEQ + t0) * HD + d) = v0;
                *(float2*)(dst + (((size_t)(bb1 * N_HEADS + h)) * SEQ + t1) * HD + d) = v1;
            }
        }
    }
}

// ---------------------------------------------------------------------------
// Flash attention via tf32 mma.sync. CTA = 128 q-rows of one (b,h), 8 warps.
// Key tiles of 64. Warp w owns q-rows [w*16, w*16+16).
// Smem (dynamic): Qs[128][68], Ks[64][68], Vt[64][68] (d-major), Ps[128][68].
// Stride 68 = 4 (mod 32) -> conflict-free fragment loads.
// Q pre-scaled by 0.125*log2e so softmax runs in exp2 domain.
// ---------------------------------------------------------------------------
#define LDF 68
#define FLASH_SMEM ((128 * LDF + 64 * LDF + 64 * LDF + 128 * LDF) * 4)

__global__ void __launch_bounds__(256, 2)
flash_mma()
{
    extern __shared__ uint32_t fsm[];
    uint32_t* Qs = fsm;                      // [128][LDF]
    uint32_t* Ks = Qs + 128 * LDF;           // [64][LDF]  (key-major, d cols)
    uint32_t* Vt = Ks + 64 * LDF;            // [64][LDF]  (d-major, key cols)
    uint32_t* Ps = Vt + 64 * LDF;            // [128][LDF]

    const int tid  = threadIdx.x;
    const int wid  = tid >> 5;
    const int lane = tid & 31;
    const int g    = lane >> 2;
    const int tig  = lane & 3;
    const int qt   = (int)gridDim.x - 1 - (int)blockIdx.x;  // heavy first
    const int bh   = blockIdx.y;
    const int q0   = qt * 128;

    const float QSCALE = 0.125f * 1.44269504f;  // 1/sqrt(64) * log2(e)

    // Stage Q (scaled, tf32)
    {
        const int row = tid >> 1;
        const int d0  = (tid & 1) * 32;
        const float* src = g_Q + ((size_t)bh * SEQ + q0 + row) * HD + d0;
#pragma unroll
        for (int i = 0; i < 8; i++) {
            float4 v = *(const float4*)(src + i * 4);
            uint4 t = make_uint4(f2tf32(v.x * QSCALE), f2tf32(v.y * QSCALE),
                                 f2tf32(v.z * QSCALE), f2tf32(v.w * QSCALE));
            *(uint4*)&Qs[row * LDF + d0 + i * 4] = t;
        }
    }

    float mrow[2], lrow[2], Of[8][4];
    mrow[0] = mrow[1] = -1e30f;
    lrow[0] = lrow[1] = 0.0f;
#pragma unroll
    for (int nf = 0; nf < 8; nf++)
#pragma unroll
        for (int r = 0; r < 4; r++) Of[nf][r] = 0.0f;

    const int rowA = wid * 16 + g;     // in-tile row of accum row 0
    const int nt   = qt * 2 + 2;       // key tiles needed

    for (int kt = 0; kt < nt; kt++) {
        const int n0 = kt * 64;
        __syncthreads();  // prior tile's Vt/Ps reads complete (covers Q 1st iter)

        // Stage K [key][d] and V transposed [d][key]
        {
            const int key = tid >> 2;
            const int d0  = (tid & 3) * 16;
            const float* ks = g_K + ((size_t)bh * SEQ + n0 + key) * HD + d0;
            const float* vs = g_V + ((size_t)bh * SEQ + n0 + key) * HD + d0;
#pragma unroll
            for (int i = 0; i < 4; i++) {
                float4 v = *(const float4*)(ks + i * 4);
                uint4 t = make_uint4(f2tf32(v.x), f2tf32(v.y),
                                     f2tf32(v.z), f2tf32(v.w));
                *(uint4*)&Ks[key * LDF + d0 + i * 4] = t;
            }
#pragma unroll
            for (int i = 0; i < 16; i += 4) {
                float4 v = *(const float4*)(vs + i);
                Vt[(d0 + i + 0) * LDF + key] = f2tf32(v.x);
                Vt[(d0 + i + 1) * LDF + key] = f2tf32(v.y);
                Vt[(d0 + i + 2) * LDF + key] = f2tf32(v.z);
                Vt[(d0 + i + 3) * LDF + key] = f2tf32(v.w);
            }
        }
        __syncthreads();

        // S = Q K^T  (warp: m16 x n64, k=64)
        float sacc[8][4];
#pragma unroll
        for (int nf = 0; nf < 8; nf++)
#pragma unroll
            for (int r = 0; r < 4; r++) sacc[nf][r] = 0.0f;

#pragma unroll
        for (int kc = 0; kc < 8; kc++) {
            uint32_t a[4];
            a[0] = Qs[rowA * LDF + kc * 8 + tig];
            a[1] = Qs[(rowA + 8) * LDF + kc * 8 + tig];
            a[2] = Qs[rowA * LDF + kc * 8 + tig + 4];
            a[3] = Qs[(rowA + 8) * LDF + kc * 8 + tig + 4];
#pragma unroll
            for (int nf = 0; nf < 8; nf++) {
                uint32_t b[2];
                b[0] = Ks[(nf * 8 + g) * LDF + kc * 8 + tig];
                b[1] = Ks[(nf * 8 + g) * LDF + kc * 8 + tig + 4];
                mma_tf32(sacc[nf], a, b);
            }
        }

        // Causal mask (only diagonal band tiles)
        if (kt >= nt - 2) {
            const int r0g = q0 + rowA;
#pragma unroll
            for (int nf = 0; nf < 8; nf++) {
                const int c0 = n0 + nf * 8 + 2 * tig;
                if (c0     > r0g)     sacc[nf][0] = -1e30f;
                if (c0 + 1 > r0g)     sacc[nf][1] = -1e30f;
                if (c0     > r0g + 8) sacc[nf][2] = -1e30f;
                if (c0 + 1 > r0g + 8) sacc[nf][3] = -1e30f;
            }
        }

        // Online softmax (rows rowA, rowA+8). Lanes sharing a row = tig group.
        float rm0 = -1e30f, rm1 = -1e30f;
#pragma unroll
        for (int nf = 0; nf < 8; nf++) {
            rm0 = fmaxf(rm0, fmaxf(sacc[nf][0], sacc[nf][1]));
            rm1 = fmaxf(rm1, fmaxf(sacc[nf][2], sacc[nf][3]));
        }
        rm0 = fmaxf(rm0, __shfl_xor_sync(0xffffffffu, rm0, 1));
        rm0 = fmaxf(rm0, __shfl_xor_sync(0xffffffffu, rm0, 2));
        rm1 = fmaxf(rm1, __shfl_xor_sync(0xffffffffu, rm1, 1));
        rm1 = fmaxf(rm1, __shfl_xor_sync(0xffffffffu, rm1, 2));

        const float nm0 = fmaxf(mrow[0], rm0);
        const float nm1 = fmaxf(mrow[1], rm1);
        const float al0 = exp2f(mrow[0] - nm0);
        const float al1 = exp2f(mrow[1] - nm1);
        mrow[0] = nm0; mrow[1] = nm1;

        float rs0 = 0.0f, rs1 = 0.0f;
#pragma unroll
        for (int nf = 0; nf < 8; nf++) {
            const float p0 = exp2f(sacc[nf][0] - nm0);
            const float p1 = exp2f(sacc[nf][1] - nm0);
            const float p2 = exp2f(sacc[nf][2] - nm1);
            const float p3 = exp2f(sacc[nf][3] - nm1);
            rs0 += p0 + p1;
            rs1 += p2 + p3;
            const int col = nf * 8 + 2 * tig;
            *(uint2*)&Ps[rowA * LDF + col] = make_uint2(f2tf32(p0), f2tf32(p1));
            *(uint2*)&Ps[(rowA + 8) * LDF + col] = make_uint2(f2tf32(p2), f2tf32(p3));
        }
        rs0 += __shfl_xor_sync(0xffffffffu, rs0, 1);
        rs0 += __shfl_xor_sync(0xffffffffu, rs0, 2);
        rs1 += __shfl_xor_sync(0xffffffffu, rs1, 1);
        rs1 += __shfl_xor_sync(0xffffffffu, rs1, 2);
        lrow[0] = lrow[0] * al0 + rs0;
        lrow[1] = lrow[1] * al1 + rs1;

#pragma unroll
        for (int nf = 0; nf < 8; nf++) {
            Of[nf][0] *= al0; Of[nf][1] *= al0;
            Of[nf][2] *= al1; Of[nf][3] *= al1;
        }

        __syncwarp();  // P stores visible to warp (each warp reads only own rows)

        // O += P V   (A = Ps rows of this warp, B = Vt[d][key])
#pragma unroll
        for (int kc = 0; kc < 8; kc++) {
            uint32_t a[4];
            a[0] = Ps[rowA * LDF + kc * 8 + tig];
            a[1] = Ps[(rowA + 8) * LDF + kc * 8 + tig];
            a[2] = Ps[rowA * LDF + kc * 8 + tig + 4];
            a[3] = Ps[(rowA + 8) * LDF + kc * 8 + tig + 4];
#pragma unroll
            for (int nf = 0; nf < 8; nf++) {
                uint32_t b[2];
                b[0] = Vt[(nf * 8 + g) * LDF + kc * 8 + tig];
                b[1] = Vt[(nf * 8 + g) * LDF + kc * 8 + tig + 4];
                mma_tf32(Of[nf], a, b);
            }
        }
    }

    // Epilogue: normalize and write Y[b, t, h*64 + d]
    const float inv0 = 1.0f / lrow[0];
    const float inv1 = 1.0f / lrow[1];
    const int b = bh >> 4;
    const int h = bh & 15;
    const int t0 = q0 + rowA;
    const int t1 = t0 + 8;
    float* y0 = g_Y + ((size_t)b * SEQ + t0) * D_MODEL + h * 64;
    float* y1 = g_Y + ((size_t)b * SEQ + t1) * D_MODEL + h * 64;
#pragma unroll
    for (int nf = 0; nf < 8; nf++) {
        const int col = nf * 8 + 2 * tig;
        *(float2*)(y0 + col) = make_float2(Of[nf][0] * inv0, Of[nf][1] * inv0);
        *(float2*)(y1 + col) = make_float2(Of[nf][2] * inv1, Of[nf][3] * inv1);
    }
}

// ---------------------------------------------------------------------------
extern "C" void kernel_launch(void* const* d_in, const int* in_sizes, int n_in,
                              void* d_out, int out_size)
{
    const float* x      = (const float*)d_in[0];
    const float* W_attn = (const float*)d_in[1];
    const float* b_attn = (const float*)d_in[2];
    const float* W_proj = (const float*)d_in[3];
    const float* b_proj = (const float*)d_in[4];
    float* out = (float*)d_out;

    const int SMEM_BYTES = 2 * BUF_BYTES;  // 73728
    cudaFuncSetAttribute(gemm_mma<1>, cudaFuncAttributeMaxDynamicSharedMemorySize, SMEM_BYTES);
    cudaFuncSetAttribute(gemm_mma<0>, cudaFuncAttributeMaxDynamicSharedMemorySize, SMEM_BYTES);
    cudaFuncSetAttribute(flash_mma, cudaFuncAttributeMaxDynamicSharedMemorySize, FLASH_SMEM);

    float* wta; cudaGetSymbolAddress((void**)&wta, g_WTa);
    float* wtp; cudaGetSymbolAddress((void**)&wtp, g_WTp);

    // 0) Transpose weights to K-major [n][k]
    {
        dim3 blk(32, 8);
        transpose_kernel<<<dim3(3 * D_MODEL / 32, D_MODEL / 32), blk>>>(W_attn, wta, D_MODEL, 3 * D_MODEL);
        transpose_kernel<<<dim3(D_MODEL / 32, D_MODEL / 32), blk>>>(W_proj, wtp, D_MODEL, D_MODEL);
    }
    // 1) QKV projection (tf32 mma.sync) -> g_Q/g_K/g_V
    {
        dim3 grid(3 * D_MODEL / 128, M_TOK / 128);
        gemm_mma<1><<<grid, 256, SMEM_BYTES>>>(x, wta, b_attn, nullptr);
    }
    // 2) Causal flash attention (tf32 mma.sync) -> g_Y
    {
        dim3 grid(SEQ / 128, BH);  // (16, 64)
        flash_mma<<<grid, 256, FLASH_SMEM>>>();
    }
    // 3) Output projection (tf32 mma.sync) -> d_out
    {
        dim3 grid(D_MODEL / 128, M_TOK / 128);
        gemm_mma<0><<<grid, 256, SMEM_BYTES>>>(nullptr, wtp, b_proj, out);
    }
}

// round 6
// speedup vs baseline: 2.9547x; 1.0441x over previous
#include <cuda_runtime.h>
#include <math.h>
#include <stdint.h>

// Problem constants
#define D_MODEL 1024
#define N_HEADS 16
#define HD      64
#define BATCH   4
#define SEQ     2048
#define BH      (BATCH * N_HEADS)   // 64
#define M_TOK   (BATCH * SEQ)       // 8192

// Scratch (device globals: allocation-free per harness rules)
__device__ float g_Q[(size_t)BH * SEQ * HD];
__device__ float g_K[(size_t)BH * SEQ * HD];
__device__ float g_V[(size_t)BH * SEQ * HD];
__device__ float g_Y[(size_t)M_TOK * D_MODEL];
__device__ float g_WTa[(size_t)3 * D_MODEL * D_MODEL];  // W_attn^T [3072][1024]
__device__ float g_WTp[(size_t)D_MODEL * D_MODEL];      // W_proj^T [1024][1024]

// ---------------------------------------------------------------------------
// mma.sync tf32 helpers (base-target ISA; sm_80+)
// ---------------------------------------------------------------------------
__device__ __forceinline__ uint32_t f2tf32(float f) {
    uint32_t r;
    asm("cvt.rna.tf32.f32 %0, %1;" : "=r"(r) : "f"(f));
    return r;
}
__device__ __forceinline__ void mma_tf32(float d[4], const uint32_t a[4],
                                         const uint32_t b[2]) {
    asm volatile(
        "mma.sync.aligned.m16n8k8.row.col.f32.tf32.tf32.f32 "
        "{%0,%1,%2,%3}, {%4,%5,%6,%7}, {%8,%9}, {%0,%1,%2,%3};"
        : "+f"(d[0]), "+f"(d[1]), "+f"(d[2]), "+f"(d[3])
        : "r"(a[0]), "r"(a[1]), "r"(a[2]), "r"(a[3]), "r"(b[0]), "r"(b[1]));
}

// ---------------------------------------------------------------------------
// Weight transpose: W[R][C] -> WT[C][R]
// ---------------------------------------------------------------------------
__global__ void transpose_kernel(const float* __restrict__ W, float* __restrict__ WT,
                                 int R, int C)
{
    __shared__ float t[32][33];
    const int c0 = blockIdx.x * 32, r0 = blockIdx.y * 32;
    const int tx = threadIdx.x, ty = threadIdx.y;  // 32x8
#pragma unroll
    for (int i = 0; i < 32; i += 8)
        t[ty + i][tx] = W[(size_t)(r0 + ty + i) * C + c0 + tx];
    __syncthreads();
#pragma unroll
    for (int i = 0; i < 32; i += 8)
        WT[(size_t)(c0 + ty + i) * R + r0 + tx] = t[tx][ty + i];
}

// ---------------------------------------------------------------------------
// TF32 tensor-core GEMM via mma.sync (unchanged from Round 4).
// ---------------------------------------------------------------------------
#define LDW 36
#define TILE_U32 (128 * LDW)
#define BUF_BYTES (2 * TILE_U32 * 4)

template <int MODE>
__global__ void __launch_bounds__(256)
gemm_mma(const float* __restrict__ Ain, const float* __restrict__ Bt,
         const float* __restrict__ bias, float* __restrict__ Cout)
{
    constexpr int K  = D_MODEL;
    constexpr int NS = K / 32;

    const int tid  = threadIdx.x;
    const int wid  = tid >> 5;
    const int lane = tid & 31;
    const int g    = lane >> 2;
    const int tig  = lane & 3;
    const int m0   = blockIdx.y * 128;
    const int n0   = blockIdx.x * 128;
    const int wm   = (wid & 3) * 32;
    const int wn   = (wid >> 2) * 64;
    const float* A = (MODE == 0) ? g_Y : Ain;

    extern __shared__ uint32_t sm[];

    float acc[2][8][4];
#pragma unroll
    for (int mf = 0; mf < 2; mf++)
#pragma unroll
        for (int nf = 0; nf < 8; nf++)
#pragma unroll
            for (int r = 0; r < 4; r++) acc[mf][nf][r] = 0.0f;

    const float4* Ap[4];
    const float4* Bp[4];
    uint32_t soff[4];
#pragma unroll
    for (int i = 0; i < 4; i++) {
        const int idx = tid + 256 * i;
        const int row = idx >> 3, c4 = idx & 7;
        Ap[i] = (const float4*)(A  + (size_t)(m0 + row) * K + c4 * 4);
        Bp[i] = (const float4*)(Bt + (size_t)(n0 + row) * K + c4 * 4);
        soff[i] = row * LDW + c4 * 4;
    }

    float4 ra[4], rb[4];
#pragma unroll
    for (int i = 0; i < 4; i++) { ra[i] = Ap[i][0]; rb[i] = Bp[i][0]; }
#pragma unroll
    for (int i = 0; i < 4; i++) {
        uint4 av = make_uint4(f2tf32(ra[i].x), f2tf32(ra[i].y),
                              f2tf32(ra[i].z), f2tf32(ra[i].w));
        uint4 bv = make_uint4(f2tf32(rb[i].x), f2tf32(rb[i].y),
                              f2tf32(rb[i].z), f2tf32(rb[i].w));
        *(uint4*)&sm[soff[i]]            = av;
        *(uint4*)&sm[TILE_U32 + soff[i]] = bv;
    }
    __syncthreads();

    for (int s = 0; s < NS; s++) {
        if (s + 1 < NS) {
#pragma unroll
            for (int i = 0; i < 4; i++) {
                ra[i] = Ap[i][(s + 1) * 8];
                rb[i] = Bp[i][(s + 1) * 8];
            }
        }

        const uint32_t* As = sm + (uint32_t)(s & 1) * (2 * TILE_U32);
        const uint32_t* Bs = As + TILE_U32;
#pragma unroll
        for (int ks = 0; ks < 4; ks++) {
            const int kb = ks * 8;
            uint32_t afr[2][4];
#pragma unroll
            for (int mf = 0; mf < 2; mf++) {
                const int r0i = wm + mf * 16 + g;
                afr[mf][0] = As[r0i * LDW + kb + tig];
                afr[mf][1] = As[(r0i + 8) * LDW + kb + tig];
                afr[mf][2] = As[r0i * LDW + kb + tig + 4];
                afr[mf][3] = As[(r0i + 8) * LDW + kb + tig + 4];
            }
            uint32_t bfr[8][2];
#pragma unroll
            for (int nf = 0; nf < 8; nf++) {
                const int nr = wn + nf * 8 + g;
                bfr[nf][0] = Bs[nr * LDW + kb + tig];
                bfr[nf][1] = Bs[nr * LDW + kb + tig + 4];
            }
#pragma unroll
            for (int mf = 0; mf < 2; mf++)
#pragma unroll
                for (int nf = 0; nf < 8; nf++)
                    mma_tf32(acc[mf][nf], afr[mf], bfr[nf]);
        }

        if (s + 1 < NS) {
            __syncthreads();
            uint32_t* dst = sm + (uint32_t)((s + 1) & 1) * (2 * TILE_U32);
#pragma unroll
            for (int i = 0; i < 4; i++) {
                uint4 av = make_uint4(f2tf32(ra[i].x), f2tf32(ra[i].y),
                                      f2tf32(ra[i].z), f2tf32(ra[i].w));
                uint4 bv = make_uint4(f2tf32(rb[i].x), f2tf32(rb[i].y),
                                      f2tf32(rb[i].z), f2tf32(rb[i].w));
                *(uint4*)&dst[soff[i]]            = av;
                *(uint4*)&dst[TILE_U32 + soff[i]] = bv;
            }
            __syncthreads();
        }
    }

#pragma unroll
    for (int mf = 0; mf < 2; mf++) {
        const int row0 = m0 + wm + mf * 16 + g;
#pragma unroll
        for (int nf = 0; nf < 8; nf++) {
            const int col = n0 + wn + nf * 8 + 2 * tig;
            const float2 bv = *(const float2*)(bias + col);
            float2 v0 = make_float2(acc[mf][nf][0] + bv.x, acc[mf][nf][1] + bv.y);
            float2 v1 = make_float2(acc[mf][nf][2] + bv.x, acc[mf][nf][3] + bv.y);
            if (MODE == 0) {
                *(float2*)(Cout + (size_t)row0 * D_MODEL + col)       = v0;
                *(float2*)(Cout + (size_t)(row0 + 8) * D_MODEL + col) = v1;
            } else {
                const int which = col >> 10;
                const int c2    = col & 1023;
                const int h     = c2 >> 6;
                const int d     = c2 & 63;
                float* dst = (which == 0) ? g_Q : (which == 1) ? g_K : g_V;
                const int bb0 = row0 >> 11, t0 = row0 & 2047;
                const int r1  = row0 + 8;
                const int bb1 = r1 >> 11,   t1 = r1 & 2047;
                *(float2*)(dst + (((size_t)(bb0 * N_HEADS + h)) * SEQ + t0) * HD + d) = v0;
                *(float2*)(dst + (((size_t)(bb1 * N_HEADS + h)) * SEQ + t1) * HD + d) = v1;
            }
        }
    }
}

// ---------------------------------------------------------------------------
// Flash attention via tf32 mma.sync. CTA = 128 q-rows of one (b,h), 8 warps.
// Key tiles of 64. Warp w owns q-rows [w*16, w*16+16).
//
// Round-6 changes vs Round 5:
//  * P stays in registers: PV A-fragments built via intra-quad shuffles of the
//    softmaxed S accumulator (no Ps smem buffer, no P store/reload).
//  * K and V staged in fragment-packed layout: per (8-n block nf, 16-k block
//    kp), lane (g,t) owns uint4 = {b0(kc=2kp), b1(kc=2kp), b0(kc=2kp+1),
//    b1(kc=2kp+1)} -> B-fragments load as one LDS.128 per (nf,kp).
//    Block stride 132 u32 keeps both staging stores and fragment loads
//    conflict-free.
// ---------------------------------------------------------------------------
#define LDF 68
#define KPB 132                          // u32 per packed (nf,kp) block
#define PACK_U32 (32 * KPB)              // 8 nf * 4 kp blocks
#define FLASH_SMEM ((128 * LDF + 2 * PACK_U32) * 4)

__global__ void __launch_bounds__(256, 2)
flash_mma()
{
    extern __shared__ uint32_t fsm[];
    uint32_t* Qs = fsm;                  // [128][LDF] row-major tf32
    uint32_t* Kp = Qs + 128 * LDF;       // packed K fragments
    uint32_t* Vp = Kp + PACK_U32;        // packed V fragments (n = d dim)

    const int tid  = threadIdx.x;
    const int wid  = tid >> 5;
    const int lane = tid & 31;
    const int g    = lane >> 2;
    const int tig  = lane & 3;
    const int qt   = (int)gridDim.x - 1 - (int)blockIdx.x;  // heavy first
    const int bh   = blockIdx.y;
    const int q0   = qt * 128;

    const float QSCALE = 0.125f * 1.44269504f;  // 1/sqrt(64) * log2(e)

    // Stage Q (scaled, tf32)
    {
        const int row = tid >> 1;
        const int d0  = (tid & 1) * 32;
        const float* src = g_Q + ((size_t)bh * SEQ + q0 + row) * HD + d0;
#pragma unroll
        for (int i = 0; i < 8; i++) {
            float4 v = *(const float4*)(src + i * 4);
            uint4 t = make_uint4(f2tf32(v.x * QSCALE), f2tf32(v.y * QSCALE),
                                 f2tf32(v.z * QSCALE), f2tf32(v.w * QSCALE));
            *(uint4*)&Qs[row * LDF + d0 + i * 4] = t;
        }
    }

    float mrow[2], lrow[2], Of[8][4];
    mrow[0] = mrow[1] = -1e30f;
    lrow[0] = lrow[1] = 0.0f;
#pragma unroll
    for (int nf = 0; nf < 8; nf++)
#pragma unroll
        for (int r = 0; r < 4; r++) Of[nf][r] = 0.0f;

    const int rowA = wid * 16 + g;     // in-tile row of accum row 0
    const int nt   = qt * 2 + 2;       // key tiles needed

    // Staging maps (per thread): key = tid>>2 in 0..63, covers 16 d-columns
    const int skey = tid >> 2;
    const int skp  = tid & 3;          // for K: kp block; d0 = skp*16
    const int sg   = skey & 7;
    const int snf  = skey >> 3;
    const int kstore = (snf * 4 + skp) * KPB + sg * 16;   // + w*4 + i
    // V: element (d, key): idx = ((d>>3)*4 + (key>>4))*KPB + ((d&7)*4 + (key&3))*4 + ((key>>2)&3)
    const int vkp  = skey >> 4;
    const int vt4  = (skey & 3) * 4;
    const int vslot = (skey >> 2) & 3;

    for (int kt = 0; kt < nt; kt++) {
        const int n0 = kt * 64;
        __syncthreads();  // prior tile's fragment reads complete (covers Q 1st iter)

        // Stage K packed
        {
            const float* ks = g_K + ((size_t)bh * SEQ + n0 + skey) * HD + skp * 16;
#pragma unroll
            for (int i = 0; i < 4; i++) {
                float4 v = *(const float4*)(ks + i * 4);
                Kp[kstore + 0  + i] = f2tf32(v.x);
                Kp[kstore + 4  + i] = f2tf32(v.y);
                Kp[kstore + 8  + i] = f2tf32(v.z);
                Kp[kstore + 12 + i] = f2tf32(v.w);
            }
        }
        // Stage V packed (n-dim = d, k-dim = key)
        {
            const int d0 = skp * 16;
            const float* vs = g_V + ((size_t)bh * SEQ + n0 + skey) * HD + d0;
#pragma unroll
            for (int i = 0; i < 4; i++) {
                float4 v = *(const float4*)(vs + i * 4);
                const float vv[4] = {v.x, v.y, v.z, v.w};
#pragma unroll
                for (int w = 0; w < 4; w++) {
                    const int d = d0 + i * 4 + w;
                    Vp[((d >> 3) * 4 + vkp) * KPB + ((d & 7) * 4 + (vt4 >> 2)) * 4 + vslot]
                        = f2tf32(vv[w]);
                }
            }
        }
        __syncthreads();

        // ---- S = Q K^T  (warp: m16 x n64, k=64) ----
        float sacc[8][4];
#pragma unroll
        for (int nf = 0; nf < 8; nf++)
#pragma unroll
            for (int r = 0; r < 4; r++) sacc[nf][r] = 0.0f;

#pragma unroll
        for (int kp = 0; kp < 4; kp++) {
            uint32_t aq[2][4];
#pragma unroll
            for (int h = 0; h < 2; h++) {
                const int kb8 = (kp * 2 + h) * 8;
                aq[h][0] = Qs[rowA * LDF + kb8 + tig];
                aq[h][1] = Qs[(rowA + 8) * LDF + kb8 + tig];
                aq[h][2] = Qs[rowA * LDF + kb8 + tig + 4];
                aq[h][3] = Qs[(rowA + 8) * LDF + kb8 + tig + 4];
            }
#pragma unroll
            for (int half = 0; half < 2; half++) {
                uint4 kb[4];
#pragma unroll
                for (int i = 0; i < 4; i++)
                    kb[i] = *(const uint4*)&Kp[((half * 4 + i) * 4 + kp) * KPB + lane * 4];
#pragma unroll
                for (int h = 0; h < 2; h++)
#pragma unroll
                    for (int i = 0; i < 4; i++) {
                        uint32_t b[2];
                        b[0] = h ? kb[i].z : kb[i].x;
                        b[1] = h ? kb[i].w : kb[i].y;
                        mma_tf32(sacc[half * 4 + i], aq[h], b);
                    }
            }
        }

        // Causal mask (only diagonal band tiles)
        if (kt >= nt - 2) {
            const int r0g = q0 + rowA;
#pragma unroll
            for (int nf = 0; nf < 8; nf++) {
                const int c0 = n0 + nf * 8 + 2 * tig;
                if (c0     > r0g)     sacc[nf][0] = -1e30f;
                if (c0 + 1 > r0g)     sacc[nf][1] = -1e30f;
                if (c0     > r0g + 8) sacc[nf][2] = -1e30f;
                if (c0 + 1 > r0g + 8) sacc[nf][3] = -1e30f;
            }
        }

        // ---- Online softmax (rows rowA, rowA+8); tig group shares a row ----
        float rm0 = -1e30f, rm1 = -1e30f;
#pragma unroll
        for (int nf = 0; nf < 8; nf++) {
            rm0 = fmaxf(rm0, fmaxf(sacc[nf][0], sacc[nf][1]));
            rm1 = fmaxf(rm1, fmaxf(sacc[nf][2], sacc[nf][3]));
        }
        rm0 = fmaxf(rm0, __shfl_xor_sync(0xffffffffu, rm0, 1));
        rm0 = fmaxf(rm0, __shfl_xor_sync(0xffffffffu, rm0, 2));
        rm1 = fmaxf(rm1, __shfl_xor_sync(0xffffffffu, rm1, 1));
        rm1 = fmaxf(rm1, __shfl_xor_sync(0xffffffffu, rm1, 2));

        const float nm0 = fmaxf(mrow[0], rm0);
        const float nm1 = fmaxf(mrow[1], rm1);
        const float al0 = exp2f(mrow[0] - nm0);
        const float al1 = exp2f(mrow[1] - nm1);
        mrow[0] = nm0; mrow[1] = nm1;

        // P in registers (tf32) + row sums
        uint32_t P0[8], P1[8], P2[8], P3[8];
        float rs0 = 0.0f, rs1 = 0.0f;
#pragma unroll
        for (int nf = 0; nf < 8; nf++) {
            const float p0 = exp2f(sacc[nf][0] - nm0);
            const float p1 = exp2f(sacc[nf][1] - nm0);
            const float p2 = exp2f(sacc[nf][2] - nm1);
            const float p3 = exp2f(sacc[nf][3] - nm1);
            rs0 += p0 + p1;
            rs1 += p2 + p3;
            P0[nf] = f2tf32(p0); P1[nf] = f2tf32(p1);
            P2[nf] = f2tf32(p2); P3[nf] = f2tf32(p3);
        }
        rs0 += __shfl_xor_sync(0xffffffffu, rs0, 1);
        rs0 += __shfl_xor_sync(0xffffffffu, rs0, 2);
        rs1 += __shfl_xor_sync(0xffffffffu, rs1, 1);
        rs1 += __shfl_xor_sync(0xffffffffu, rs1, 2);
        lrow[0] = lrow[0] * al0 + rs0;
        lrow[1] = lrow[1] * al1 + rs1;

#pragma unroll
        for (int nf = 0; nf < 8; nf++) {
            Of[nf][0] *= al0; Of[nf][1] *= al0;
            Of[nf][2] *= al1; Of[nf][3] *= al1;
        }

        // ---- O += P V  (A = P via shuffles, B = packed V) ----
        const int srcA = (lane & 28) | (tig >> 1);
        const int srcB = srcA + 2;
        const bool hi  = (tig & 1);
#pragma unroll
        for (int kp = 0; kp < 4; kp++) {
            uint32_t ap[2][4];
#pragma unroll
            for (int h = 0; h < 2; h++) {
                const int kc = kp * 2 + h;
                uint32_t x0 = __shfl_sync(0xffffffffu, P0[kc], srcA);
                uint32_t x1 = __shfl_sync(0xffffffffu, P1[kc], srcA);
                uint32_t y0 = __shfl_sync(0xffffffffu, P2[kc], srcA);
                uint32_t y1 = __shfl_sync(0xffffffffu, P3[kc], srcA);
                uint32_t z0 = __shfl_sync(0xffffffffu, P0[kc], srcB);
                uint32_t z1 = __shfl_sync(0xffffffffu, P1[kc], srcB);
                uint32_t w0 = __shfl_sync(0xffffffffu, P2[kc], srcB);
                uint32_t w1 = __shfl_sync(0xffffffffu, P3[kc], srcB);
                ap[h][0] = hi ? x1 : x0;
                ap[h][1] = hi ? y1 : y0;
                ap[h][2] = hi ? z1 : z0;
                ap[h][3] = hi ? w1 : w0;
            }
#pragma unroll
            for (int half = 0; half < 2; half++) {
                uint4 vb[4];
#pragma unroll
                for (int i = 0; i < 4; i++)
                    vb[i] = *(const uint4*)&Vp[((half * 4 + i) * 4 + kp) * KPB + lane * 4];
#pragma unroll
                for (int h = 0; h < 2; h++)
#pragma unroll
                    for (int i = 0; i < 4; i++) {
                        uint32_t b[2];
                        b[0] = h ? vb[i].z : vb[i].x;
                        b[1] = h ? vb[i].w : vb[i].y;
                        mma_tf32(Of[half * 4 + i], ap[h], b);
                    }
            }
        }
    }

    // Epilogue: normalize and write Y[b, t, h*64 + d]
    const float inv0 = 1.0f / lrow[0];
    const float inv1 = 1.0f / lrow[1];
    const int b = bh >> 4;
    const int h = bh & 15;
    const int t0 = q0 + rowA;
    const int t1 = t0 + 8;
    float* y0 = g_Y + ((size_t)b * SEQ + t0) * D_MODEL + h * 64;
    float* y1 = g_Y + ((size_t)b * SEQ + t1) * D_MODEL + h * 64;
#pragma unroll
    for (int nf = 0; nf < 8; nf++) {
        const int col = nf * 8 + 2 * tig;
        *(float2*)(y0 + col) = make_float2(Of[nf][0] * inv0, Of[nf][1] * inv0);
        *(float2*)(y1 + col) = make_float2(Of[nf][2] * inv1, Of[nf][3] * inv1);
    }
}

// ---------------------------------------------------------------------------
extern "C" void kernel_launch(void* const* d_in, const int* in_sizes, int n_in,
                              void* d_out, int out_size)
{
    const float* x      = (const float*)d_in[0];
    const float* W_attn = (const float*)d_in[1];
    const float* b_attn = (const float*)d_in[2];
    const float* W_proj = (const float*)d_in[3];
    const float* b_proj = (const float*)d_in[4];
    float* out = (float*)d_out;

    const int SMEM_BYTES = 2 * BUF_BYTES;  // 73728
    cudaFuncSetAttribute(gemm_mma<1>, cudaFuncAttributeMaxDynamicSharedMemorySize, SMEM_BYTES);
    cudaFuncSetAttribute(gemm_mma<0>, cudaFuncAttributeMaxDynamicSharedMemorySize, SMEM_BYTES);
    cudaFuncSetAttribute(flash_mma, cudaFuncAttributeMaxDynamicSharedMemorySize, FLASH_SMEM);

    float* wta; cudaGetSymbolAddress((void**)&wta, g_WTa);
    float* wtp; cudaGetSymbolAddress((void**)&wtp, g_WTp);

    // 0) Transpose weights to K-major [n][k]
    {
        dim3 blk(32, 8);
        transpose_kernel<<<dim3(3 * D_MODEL / 32, D_MODEL / 32), blk>>>(W_attn, wta, D_MODEL, 3 * D_MODEL);
        transpose_kernel<<<dim3(D_MODEL / 32, D_MODEL / 32), blk>>>(W_proj, wtp, D_MODEL, D_MODEL);
    }
    // 1) QKV projection (tf32 mma.sync) -> g_Q/g_K/g_V
    {
        dim3 grid(3 * D_MODEL / 128, M_TOK / 128);
        gemm_mma<1><<<grid, 256, SMEM_BYTES>>>(x, wta, b_attn, nullptr);
    }
    // 2) Causal flash attention (tf32 mma.sync) -> g_Y
    {
        dim3 grid(SEQ / 128, BH);  // (16, 64)
        flash_mma<<<grid, 256, FLASH_SMEM>>>();
    }
    // 3) Output projection (tf32 mma.sync) -> d_out
    {
        dim3 grid(D_MODEL / 128, M_TOK / 128);
        gemm_mma<0><<<grid, 256, SMEM_BYTES>>>(nullptr, wtp, b_proj, out);
    }
}

// round 7
// speedup vs baseline: 3.1410x; 1.0630x over previous
#include <cuda_runtime.h>
#include <math.h>
#include <stdint.h>

// Problem constants
#define D_MODEL 1024
#define N_HEADS 16
#define HD      64
#define BATCH   4
#define SEQ     2048
#define BH      (BATCH * N_HEADS)   // 64
#define M_TOK   (BATCH * SEQ)       // 8192

// Scratch (device globals: allocation-free per harness rules)
__device__ float g_Q[(size_t)BH * SEQ * HD];
__device__ float g_K[(size_t)BH * SEQ * HD];
__device__ float g_V[(size_t)BH * SEQ * HD];
__device__ float g_Y[(size_t)M_TOK * D_MODEL];
__device__ float g_WTa[(size_t)3 * D_MODEL * D_MODEL];  // W_attn^T [3072][1024]
__device__ float g_WTp[(size_t)D_MODEL * D_MODEL];      // W_proj^T [1024][1024]

// ---------------------------------------------------------------------------
// mma.sync tf32 helpers (base-target ISA; sm_80+)
// ---------------------------------------------------------------------------
__device__ __forceinline__ uint32_t f2tf32(float f) {
    uint32_t r;
    asm("cvt.rna.tf32.f32 %0, %1;" : "=r"(r) : "f"(f));
    return r;
}
__device__ __forceinline__ void mma_tf32(float d[4], const uint32_t a[4],
                                         const uint32_t b[2]) {
    asm volatile(
        "mma.sync.aligned.m16n8k8.row.col.f32.tf32.tf32.f32 "
        "{%0,%1,%2,%3}, {%4,%5,%6,%7}, {%8,%9}, {%0,%1,%2,%3};"
        : "+f"(d[0]), "+f"(d[1]), "+f"(d[2]), "+f"(d[3])
        : "r"(a[0]), "r"(a[1]), "r"(a[2]), "r"(a[3]), "r"(b[0]), "r"(b[1]));
}

// ---------------------------------------------------------------------------
// Weight transpose: W[R][C] -> WT[C][R]
// ---------------------------------------------------------------------------
__global__ void transpose_kernel(const float* __restrict__ W, float* __restrict__ WT,
                                 int R, int C)
{
    __shared__ float t[32][33];
    const int c0 = blockIdx.x * 32, r0 = blockIdx.y * 32;
    const int tx = threadIdx.x, ty = threadIdx.y;  // 32x8
#pragma unroll
    for (int i = 0; i < 32; i += 8)
        t[ty + i][tx] = W[(size_t)(r0 + ty + i) * C + c0 + tx];
    __syncthreads();
#pragma unroll
    for (int i = 0; i < 32; i += 8)
        WT[(size_t)(c0 + ty + i) * R + r0 + tx] = t[tx][ty + i];
}

// ---------------------------------------------------------------------------
// TF32 tensor-core GEMM via mma.sync (unchanged from Round 4).
// ---------------------------------------------------------------------------
#define LDW 36
#define TILE_U32 (128 * LDW)
#define BUF_BYTES (2 * TILE_U32 * 4)

template <int MODE>
__global__ void __launch_bounds__(256)
gemm_mma(const float* __restrict__ Ain, const float* __restrict__ Bt,
         const float* __restrict__ bias, float* __restrict__ Cout)
{
    constexpr int K  = D_MODEL;
    constexpr int NS = K / 32;

    const int tid  = threadIdx.x;
    const int wid  = tid >> 5;
    const int lane = tid & 31;
    const int g    = lane >> 2;
    const int tig  = lane & 3;
    const int m0   = blockIdx.y * 128;
    const int n0   = blockIdx.x * 128;
    const int wm   = (wid & 3) * 32;
    const int wn   = (wid >> 2) * 64;
    const float* A = (MODE == 0) ? g_Y : Ain;

    extern __shared__ uint32_t sm[];

    float acc[2][8][4];
#pragma unroll
    for (int mf = 0; mf < 2; mf++)
#pragma unroll
        for (int nf = 0; nf < 8; nf++)
#pragma unroll
            for (int r = 0; r < 4; r++) acc[mf][nf][r] = 0.0f;

    const float4* Ap[4];
    const float4* Bp[4];
    uint32_t soff[4];
#pragma unroll
    for (int i = 0; i < 4; i++) {
        const int idx = tid + 256 * i;
        const int row = idx >> 3, c4 = idx & 7;
        Ap[i] = (const float4*)(A  + (size_t)(m0 + row) * K + c4 * 4);
        Bp[i] = (const float4*)(Bt + (size_t)(n0 + row) * K + c4 * 4);
        soff[i] = row * LDW + c4 * 4;
    }

    float4 ra[4], rb[4];
#pragma unroll
    for (int i = 0; i < 4; i++) { ra[i] = Ap[i][0]; rb[i] = Bp[i][0]; }
#pragma unroll
    for (int i = 0; i < 4; i++) {
        uint4 av = make_uint4(f2tf32(ra[i].x), f2tf32(ra[i].y),
                              f2tf32(ra[i].z), f2tf32(ra[i].w));
        uint4 bv = make_uint4(f2tf32(rb[i].x), f2tf32(rb[i].y),
                              f2tf32(rb[i].z), f2tf32(rb[i].w));
        *(uint4*)&sm[soff[i]]            = av;
        *(uint4*)&sm[TILE_U32 + soff[i]] = bv;
    }
    __syncthreads();

    for (int s = 0; s < NS; s++) {
        if (s + 1 < NS) {
#pragma unroll
            for (int i = 0; i < 4; i++) {
                ra[i] = Ap[i][(s + 1) * 8];
                rb[i] = Bp[i][(s + 1) * 8];
            }
        }

        const uint32_t* As = sm + (uint32_t)(s & 1) * (2 * TILE_U32);
        const uint32_t* Bs = As + TILE_U32;
#pragma unroll
        for (int ks = 0; ks < 4; ks++) {
            const int kb = ks * 8;
            uint32_t afr[2][4];
#pragma unroll
            for (int mf = 0; mf < 2; mf++) {
                const int r0i = wm + mf * 16 + g;
                afr[mf][0] = As[r0i * LDW + kb + tig];
                afr[mf][1] = As[(r0i + 8) * LDW + kb + tig];
                afr[mf][2] = As[r0i * LDW + kb + tig + 4];
                afr[mf][3] = As[(r0i + 8) * LDW + kb + tig + 4];
            }
            uint32_t bfr[8][2];
#pragma unroll
            for (int nf = 0; nf < 8; nf++) {
                const int nr = wn + nf * 8 + g;
                bfr[nf][0] = Bs[nr * LDW + kb + tig];
                bfr[nf][1] = Bs[nr * LDW + kb + tig + 4];
            }
#pragma unroll
            for (int mf = 0; mf < 2; mf++)
#pragma unroll
                for (int nf = 0; nf < 8; nf++)
                    mma_tf32(acc[mf][nf], afr[mf], bfr[nf]);
        }

        if (s + 1 < NS) {
            __syncthreads();
            uint32_t* dst = sm + (uint32_t)((s + 1) & 1) * (2 * TILE_U32);
#pragma unroll
            for (int i = 0; i < 4; i++) {
                uint4 av = make_uint4(f2tf32(ra[i].x), f2tf32(ra[i].y),
                                      f2tf32(ra[i].z), f2tf32(ra[i].w));
                uint4 bv = make_uint4(f2tf32(rb[i].x), f2tf32(rb[i].y),
                                      f2tf32(rb[i].z), f2tf32(rb[i].w));
                *(uint4*)&dst[soff[i]]            = av;
                *(uint4*)&dst[TILE_U32 + soff[i]] = bv;
            }
            __syncthreads();
        }
    }

#pragma unroll
    for (int mf = 0; mf < 2; mf++) {
        const int row0 = m0 + wm + mf * 16 + g;
#pragma unroll
        for (int nf = 0; nf < 8; nf++) {
            const int col = n0 + wn + nf * 8 + 2 * tig;
            const float2 bv = *(const float2*)(bias + col);
            float2 v0 = make_float2(acc[mf][nf][0] + bv.x, acc[mf][nf][1] + bv.y);
            float2 v1 = make_float2(acc[mf][nf][2] + bv.x, acc[mf][nf][3] + bv.y);
            if (MODE == 0) {
                *(float2*)(Cout + (size_t)row0 * D_MODEL + col)       = v0;
                *(float2*)(Cout + (size_t)(row0 + 8) * D_MODEL + col) = v1;
            } else {
                const int which = col >> 10;
                const int c2    = col & 1023;
                const int h     = c2 >> 6;
                const int d     = c2 & 63;
                float* dst = (which == 0) ? g_Q : (which == 1) ? g_K : g_V;
                const int bb0 = row0 >> 11, t0 = row0 & 2047;
                const int r1  = row0 + 8;
                const int bb1 = r1 >> 11,   t1 = r1 & 2047;
                *(float2*)(dst + (((size_t)(bb0 * N_HEADS + h)) * SEQ + t0) * HD + d) = v0;
                *(float2*)(dst + (((size_t)(bb1 * N_HEADS + h)) * SEQ + t1) * HD + d) = v1;
            }
        }
    }
}

// ---------------------------------------------------------------------------
// Flash attention via tf32 mma.sync.
// Round-7: CTA = 256 q-rows, 8 warps, warp = 32 q-rows (2 m-frags) so each
// shared K/V fragment load feeds 2x the MMAs (B-redundancy per q-row halved).
// K/V staged via register-prefetch: next tile's LDGs issue before compute and
// land in smem after the tail sync, hiding global latency at 1 CTA/SM.
// P stays in registers (quad shuffles). K/V fragment-packed (LDS.128 loads).
// ---------------------------------------------------------------------------
#define LDF 68
#define KPB 132                          // u32 per packed (nf,kp) block
#define PACK_U32 (32 * KPB)              // 8 nf * 4 kp blocks
#define QROWS 256
#define FLASH_SMEM ((QROWS * LDF + 2 * PACK_U32) * 4)

__global__ void __launch_bounds__(256, 1)
flash_mma()
{
    extern __shared__ uint32_t fsm[];
    uint32_t* Qs = fsm;                  // [QROWS][LDF] row-major tf32
    uint32_t* Kp = Qs + QROWS * LDF;     // packed K fragments
    uint32_t* Vp = Kp + PACK_U32;        // packed V fragments (n = d dim)

    const int tid  = threadIdx.x;
    const int wid  = tid >> 5;
    const int lane = tid & 31;
    const int g    = lane >> 2;
    const int tig  = lane & 3;
    const int qt   = (int)gridDim.x - 1 - (int)blockIdx.x;  // heavy first
    const int bh   = blockIdx.y;
    const int q0   = qt * QROWS;

    const float QSCALE = 0.125f * 1.44269504f;  // 1/sqrt(64) * log2(e)

    // Stage Q (scaled, tf32): one row per thread
    {
        const int row = tid;
        const float* src = g_Q + ((size_t)bh * SEQ + q0 + row) * HD;
#pragma unroll
        for (int i = 0; i < 16; i++) {
            float4 v = *(const float4*)(src + i * 4);
            uint4 t = make_uint4(f2tf32(v.x * QSCALE), f2tf32(v.y * QSCALE),
                                 f2tf32(v.z * QSCALE), f2tf32(v.w * QSCALE));
            *(uint4*)&Qs[row * LDF + i * 4] = t;
        }
    }

    float mrow[2][2], lrow[2][2], Of[2][8][4];
#pragma unroll
    for (int mf = 0; mf < 2; mf++) {
        mrow[mf][0] = mrow[mf][1] = -1e30f;
        lrow[mf][0] = lrow[mf][1] = 0.0f;
#pragma unroll
        for (int nf = 0; nf < 8; nf++)
#pragma unroll
            for (int r = 0; r < 4; r++) Of[mf][nf][r] = 0.0f;
    }

    const int nt = qt * 4 + 4;           // 64-key tiles needed

    // Staging maps: key = tid>>2 (0..63), 16 d-columns starting at (tid&3)*16
    const int skey = tid >> 2;
    const int skp  = tid & 3;
    const int sg   = skey & 7;
    const int snf  = skey >> 3;
    const int kstore = (snf * 4 + skp) * KPB + sg * 16;
    const int vkp  = skey >> 4;
    const int vt   = skey & 3;
    const int vslot = (skey >> 2) & 3;

    const float* kbase = g_K + (size_t)bh * SEQ * HD + (size_t)skey * HD + skp * 16;
    const float* vbase = g_V + (size_t)bh * SEQ * HD + (size_t)skey * HD + skp * 16;

    // Prefetch tile 0
    float4 pk[4], pv[4];
#pragma unroll
    for (int i = 0; i < 4; i++) {
        pk[i] = *(const float4*)(kbase + i * 4);
        pv[i] = *(const float4*)(vbase + i * 4);
    }

    for (int kt = 0; kt < nt; kt++) {
        // Store staged tile from prefetch registers (packed tf32)
#pragma unroll
        for (int i = 0; i < 4; i++) {
            Kp[kstore + 0  + i] = f2tf32(pk[i].x);
            Kp[kstore + 4  + i] = f2tf32(pk[i].y);
            Kp[kstore + 8  + i] = f2tf32(pk[i].z);
            Kp[kstore + 12 + i] = f2tf32(pk[i].w);
        }
        {
            const int d0 = skp * 16;
#pragma unroll
            for (int i = 0; i < 4; i++) {
                const float vv[4] = {pv[i].x, pv[i].y, pv[i].z, pv[i].w};
#pragma unroll
                for (int w = 0; w < 4; w++) {
                    const int d = d0 + i * 4 + w;
                    Vp[((d >> 3) * 4 + vkp) * KPB + ((d & 7) * 4 + vt) * 4 + vslot]
                        = f2tf32(vv[w]);
                }
            }
        }
        __syncthreads();

        // Issue next tile's LDGs now; they complete under the compute below.
        if (kt + 1 < nt) {
            const size_t off = (size_t)(kt + 1) * 64 * HD;
#pragma unroll
            for (int i = 0; i < 4; i++) {
                pk[i] = *(const float4*)(kbase + off + i * 4);
                pv[i] = *(const float4*)(vbase + off + i * 4);
            }
        }

        // ---- S = Q K^T  (warp: m32 x n64, k=64; B frags shared across mf) ----
        float sacc[2][8][4];
#pragma unroll
        for (int mf = 0; mf < 2; mf++)
#pragma unroll
            for (int nf = 0; nf < 8; nf++)
#pragma unroll
                for (int r = 0; r < 4; r++) sacc[mf][nf][r] = 0.0f;

#pragma unroll
        for (int kp = 0; kp < 4; kp++) {
            uint32_t aq[2][2][4];
#pragma unroll
            for (int mf = 0; mf < 2; mf++) {
                const int r0i = wid * 32 + mf * 16 + g;
#pragma unroll
                for (int h = 0; h < 2; h++) {
                    const int kb8 = (kp * 2 + h) * 8;
                    aq[mf][h][0] = Qs[r0i * LDF + kb8 + tig];
                    aq[mf][h][1] = Qs[(r0i + 8) * LDF + kb8 + tig];
                    aq[mf][h][2] = Qs[r0i * LDF + kb8 + tig + 4];
                    aq[mf][h][3] = Qs[(r0i + 8) * LDF + kb8 + tig + 4];
                }
            }
#pragma unroll
            for (int half = 0; half < 2; half++) {
                uint4 kb[4];
#pragma unroll
                for (int i = 0; i < 4; i++)
                    kb[i] = *(const uint4*)&Kp[((half * 4 + i) * 4 + kp) * KPB + lane * 4];
#pragma unroll
                for (int h = 0; h < 2; h++)
#pragma unroll
                    for (int i = 0; i < 4; i++) {
                        uint32_t b[2];
                        b[0] = h ? kb[i].z : kb[i].x;
                        b[1] = h ? kb[i].w : kb[i].y;
                        mma_tf32(sacc[0][half * 4 + i], aq[0][h], b);
                        mma_tf32(sacc[1][half * 4 + i], aq[1][h], b);
                    }
            }
        }

        // Causal mask (only tiles overlapping the diagonal band)
        if (kt >= nt - 4) {
            const int n0 = kt * 64;
#pragma unroll
            for (int mf = 0; mf < 2; mf++) {
                const int r0g = q0 + wid * 32 + mf * 16 + g;
#pragma unroll
                for (int nf = 0; nf < 8; nf++) {
                    const int c0 = n0 + nf * 8 + 2 * tig;
                    if (c0     > r0g)     sacc[mf][nf][0] = -1e30f;
                    if (c0 + 1 > r0g)     sacc[mf][nf][1] = -1e30f;
                    if (c0     > r0g + 8) sacc[mf][nf][2] = -1e30f;
                    if (c0 + 1 > r0g + 8) sacc[mf][nf][3] = -1e30f;
                }
            }
        }

        // ---- Online softmax per m-frag; tig group shares a row ----
        uint32_t P0[2][8], P1[2][8], P2[2][8], P3[2][8];
#pragma unroll
        for (int mf = 0; mf < 2; mf++) {
            float rm0 = -1e30f, rm1 = -1e30f;
#pragma unroll
            for (int nf = 0; nf < 8; nf++) {
                rm0 = fmaxf(rm0, fmaxf(sacc[mf][nf][0], sacc[mf][nf][1]));
                rm1 = fmaxf(rm1, fmaxf(sacc[mf][nf][2], sacc[mf][nf][3]));
            }
            rm0 = fmaxf(rm0, __shfl_xor_sync(0xffffffffu, rm0, 1));
            rm0 = fmaxf(rm0, __shfl_xor_sync(0xffffffffu, rm0, 2));
            rm1 = fmaxf(rm1, __shfl_xor_sync(0xffffffffu, rm1, 1));
            rm1 = fmaxf(rm1, __shfl_xor_sync(0xffffffffu, rm1, 2));

            const float nm0 = fmaxf(mrow[mf][0], rm0);
            const float nm1 = fmaxf(mrow[mf][1], rm1);
            const float al0 = exp2f(mrow[mf][0] - nm0);
            const float al1 = exp2f(mrow[mf][1] - nm1);
            mrow[mf][0] = nm0; mrow[mf][1] = nm1;

            float rs0 = 0.0f, rs1 = 0.0f;
#pragma unroll
            for (int nf = 0; nf < 8; nf++) {
                const float p0 = exp2f(sacc[mf][nf][0] - nm0);
                const float p1 = exp2f(sacc[mf][nf][1] - nm0);
                const float p2 = exp2f(sacc[mf][nf][2] - nm1);
                const float p3 = exp2f(sacc[mf][nf][3] - nm1);
                rs0 += p0 + p1;
                rs1 += p2 + p3;
                P0[mf][nf] = f2tf32(p0); P1[mf][nf] = f2tf32(p1);
                P2[mf][nf] = f2tf32(p2); P3[mf][nf] = f2tf32(p3);
            }
            rs0 += __shfl_xor_sync(0xffffffffu, rs0, 1);
            rs0 += __shfl_xor_sync(0xffffffffu, rs0, 2);
            rs1 += __shfl_xor_sync(0xffffffffu, rs1, 1);
            rs1 += __shfl_xor_sync(0xffffffffu, rs1, 2);
            lrow[mf][0] = lrow[mf][0] * al0 + rs0;
            lrow[mf][1] = lrow[mf][1] * al1 + rs1;

#pragma unroll
            for (int nf = 0; nf < 8; nf++) {
                Of[mf][nf][0] *= al0; Of[mf][nf][1] *= al0;
                Of[mf][nf][2] *= al1; Of[mf][nf][3] *= al1;
            }
        }

        // ---- O += P V  (A = P via shuffles, B = packed V shared across mf) ----
        const int srcA = (lane & 28) | (tig >> 1);
        const int srcB = srcA + 2;
        const bool hi  = (tig & 1);
#pragma unroll
        for (int kp = 0; kp < 4; kp++) {
            uint32_t ap[2][2][4];
#pragma unroll
            for (int mf = 0; mf < 2; mf++)
#pragma unroll
                for (int h = 0; h < 2; h++) {
                    const int kc = kp * 2 + h;
                    uint32_t x0 = __shfl_sync(0xffffffffu, P0[mf][kc], srcA);
                    uint32_t x1 = __shfl_sync(0xffffffffu, P1[mf][kc], srcA);
                    uint32_t y0 = __shfl_sync(0xffffffffu, P2[mf][kc], srcA);
                    uint32_t y1 = __shfl_sync(0xffffffffu, P3[mf][kc], srcA);
                    uint32_t z0 = __shfl_sync(0xffffffffu, P0[mf][kc], srcB);
                    uint32_t z1 = __shfl_sync(0xffffffffu, P1[mf][kc], srcB);
                    uint32_t w0 = __shfl_sync(0xffffffffu, P2[mf][kc], srcB);
                    uint32_t w1 = __shfl_sync(0xffffffffu, P3[mf][kc], srcB);
                    ap[mf][h][0] = hi ? x1 : x0;
                    ap[mf][h][1] = hi ? y1 : y0;
                    ap[mf][h][2] = hi ? z1 : z0;
                    ap[mf][h][3] = hi ? w1 : w0;
                }
#pragma unroll
            for (int half = 0; half < 2; half++) {
                uint4 vb[4];
#pragma unroll
                for (int i = 0; i < 4; i++)
                    vb[i] = *(const uint4*)&Vp[((half * 4 + i) * 4 + kp) * KPB + lane * 4];
#pragma unroll
                for (int h = 0; h < 2; h++)
#pragma unroll
                    for (int i = 0; i < 4; i++) {
                        uint32_t b[2];
                        b[0] = h ? vb[i].z : vb[i].x;
                        b[1] = h ? vb[i].w : vb[i].y;
                        mma_tf32(Of[0][half * 4 + i], ap[0][h], b);
                        mma_tf32(Of[1][half * 4 + i], ap[1][h], b);
                    }
            }
        }
        __syncthreads();  // all fragment reads done before next tile's STS
    }

    // Epilogue: normalize and write Y[b, t, h*64 + d]
    const int b = bh >> 4;
    const int h = bh & 15;
#pragma unroll
    for (int mf = 0; mf < 2; mf++) {
        const float inv0 = 1.0f / lrow[mf][0];
        const float inv1 = 1.0f / lrow[mf][1];
        const int t0 = q0 + wid * 32 + mf * 16 + g;
        const int t1 = t0 + 8;
        float* y0 = g_Y + ((size_t)b * SEQ + t0) * D_MODEL + h * 64;
        float* y1 = g_Y + ((size_t)b * SEQ + t1) * D_MODEL + h * 64;
#pragma unroll
        for (int nf = 0; nf < 8; nf++) {
            const int col = nf * 8 + 2 * tig;
            *(float2*)(y0 + col) = make_float2(Of[mf][nf][0] * inv0, Of[mf][nf][1] * inv0);
            *(float2*)(y1 + col) = make_float2(Of[mf][nf][2] * inv1, Of[mf][nf][3] * inv1);
        }
    }
}

// ---------------------------------------------------------------------------
extern "C" void kernel_launch(void* const* d_in, const int* in_sizes, int n_in,
                              void* d_out, int out_size)
{
    const float* x      = (const float*)d_in[0];
    const float* W_attn = (const float*)d_in[1];
    const float* b_attn = (const float*)d_in[2];
    const float* W_proj = (const float*)d_in[3];
    const float* b_proj = (const float*)d_in[4];
    float* out = (float*)d_out;

    const int SMEM_BYTES = 2 * BUF_BYTES;  // 73728
    cudaFuncSetAttribute(gemm_mma<1>, cudaFuncAttributeMaxDynamicSharedMemorySize, SMEM_BYTES);
    cudaFuncSetAttribute(gemm_mma<0>, cudaFuncAttributeMaxDynamicSharedMemorySize, SMEM_BYTES);
    cudaFuncSetAttribute(flash_mma, cudaFuncAttributeMaxDynamicSharedMemorySize, FLASH_SMEM);

    float* wta; cudaGetSymbolAddress((void**)&wta, g_WTa);
    float* wtp; cudaGetSymbolAddress((void**)&wtp, g_WTp);

    // 0) Transpose weights to K-major [n][k]
    {
        dim3 blk(32, 8);
        transpose_kernel<<<dim3(3 * D_MODEL / 32, D_MODEL / 32), blk>>>(W_attn, wta, D_MODEL, 3 * D_MODEL);
        transpose_kernel<<<dim3(D_MODEL / 32, D_MODEL / 32), blk>>>(W_proj, wtp, D_MODEL, D_MODEL);
    }
    // 1) QKV projection (tf32 mma.sync) -> g_Q/g_K/g_V
    {
        dim3 grid(3 * D_MODEL / 128, M_TOK / 128);
        gemm_mma<1><<<grid, 256, SMEM_BYTES>>>(x, wta, b_attn, nullptr);
    }
    // 2) Causal flash attention (tf32 mma.sync) -> g_Y
    {
        dim3 grid(SEQ / QROWS, BH);  // (8, 64)
        flash_mma<<<grid, 256, FLASH_SMEM>>>();
    }
    // 3) Output projection (tf32 mma.sync) -> d_out
    {
        dim3 grid(D_MODEL / 128, M_TOK / 128);
        gemm_mma<0><<<grid, 256, SMEM_BYTES>>>(nullptr, wtp, b_proj, out);
    }
}

// round 8
// speedup vs baseline: 4.0605x; 1.2927x over previous
#include <cuda_runtime.h>
#include <math.h>
#include <stdint.h>

// Problem constants
#define D_MODEL 1024
#define N_HEADS 16
#define HD      64
#define BATCH   4
#define SEQ     2048
#define BH      (BATCH * N_HEADS)   // 64
#define M_TOK   (BATCH * SEQ)       // 8192

// Scratch (device globals: allocation-free per harness rules)
__device__ float    g_Q[(size_t)BH * SEQ * HD];
__device__ float    g_K[(size_t)BH * SEQ * HD];
__device__ float    g_V[(size_t)BH * SEQ * HD];
__device__ uint32_t g_Xp[(size_t)M_TOK * D_MODEL];        // x, packed tf32 A-frag
__device__ uint32_t g_Yp[(size_t)M_TOK * D_MODEL];        // attn out, packed tf32 A-frag
__device__ uint32_t g_Wpa[(size_t)3 * D_MODEL * D_MODEL]; // W_attn^T packed tf32 B-frag
__device__ uint32_t g_Wpp[(size_t)D_MODEL * D_MODEL];     // W_proj^T packed tf32 B-frag

// ---------------------------------------------------------------------------
// Helpers (base-target ISA; sm_80+)
// ---------------------------------------------------------------------------
__device__ __forceinline__ uint32_t f2tf32(float f) {
    uint32_t r;
    asm("cvt.rna.tf32.f32 %0, %1;" : "=r"(r) : "f"(f));
    return r;
}
__device__ __forceinline__ void mma_tf32(float d[4], const uint32_t a[4],
                                         const uint32_t b[2]) {
    asm volatile(
        "mma.sync.aligned.m16n8k8.row.col.f32.tf32.tf32.f32 "
        "{%0,%1,%2,%3}, {%4,%5,%6,%7}, {%8,%9}, {%0,%1,%2,%3};"
        : "+f"(d[0]), "+f"(d[1]), "+f"(d[2]), "+f"(d[3])
        : "r"(a[0]), "r"(a[1]), "r"(a[2]), "r"(a[3]), "r"(b[0]), "r"(b[1]));
}
__device__ __forceinline__ uint32_t smem_u32(const void* p) {
    uint32_t a;
    asm("{ .reg .u64 t; cvta.to.shared.u64 t, %1; cvt.u32.u64 %0, t; }"
        : "=r"(a) : "l"(p));
    return a;
}
#define CP16(dst, src) \
    asm volatile("cp.async.cg.shared.global [%0], [%1], 16;" \
                 :: "r"(dst), "l"(src) : "memory")
#define CPCOMMIT() asm volatile("cp.async.commit_group;" ::: "memory")
#define CPWAIT1()  asm volatile("cp.async.wait_group 1;" ::: "memory")
#define CPWAIT0()  asm volatile("cp.async.wait_group 0;" ::: "memory")

// ---------------------------------------------------------------------------
// Packing kernels.
// A-packed layout (u32 units): [mb][slab][kc][lane] * 4, where mb=row/16,
//   slab=k/32, kc=(k/8)%4, lane=g*4+t; uint4 = {A[16mb+g][kb+t], A[16mb+8+g][kb+t],
//   A[16mb+g][kb+t+4], A[16mb+8+g][kb+t+4]}, kb=slab*32+kc*8.
// B-packed layout: [nb][slab][kp][lane] * 4, nb=n/8, kp=(k/16)%2;
//   uint4 = {W^T[n][k0+t], [k0+t+4], [k0+t+8], [k0+t+12]}, n=8nb+g, k0=slab*32+kp*16.
// ---------------------------------------------------------------------------
__global__ void pack_a(const float* __restrict__ X, uint32_t* __restrict__ Xp)
{
    const int i    = blockIdx.x * 256 + threadIdx.x;   // uint4 index
    const int lane = i & 31, kc = (i >> 5) & 3, slab = (i >> 7) & 31, mb = i >> 12;
    const int g = lane >> 2, t = lane & 3;
    const float* p = X + ((size_t)(mb * 16 + g)) * D_MODEL + slab * 32 + kc * 8 + t;
    uint4 o;
    o.x = f2tf32(p[0]);
    o.y = f2tf32(p[8 * D_MODEL]);
    o.z = f2tf32(p[4]);
    o.w = f2tf32(p[8 * D_MODEL + 4]);
    *(uint4*)&Xp[(size_t)i * 4] = o;
}

__global__ void pack_b(const float* __restrict__ W, uint32_t* __restrict__ Wp, int N)
{
    // W is [K=1024][N] row-major (k-major): W^T[n][k] = W[k][n]
    const int i    = blockIdx.x * 256 + threadIdx.x;
    const int lane = i & 31, kp = (i >> 5) & 1, slab = (i >> 6) & 31, nb = i >> 11;
    const int g = lane >> 2, t = lane & 3;
    const int n  = nb * 8 + g;
    const int k0 = slab * 32 + kp * 16 + t;
    const float* p = W + (size_t)k0 * N + n;
    uint4 o;
    o.x = f2tf32(p[0]);
    o.y = f2tf32(p[(size_t)4 * N]);
    o.z = f2tf32(p[(size_t)8 * N]);
    o.w = f2tf32(p[(size_t)12 * N]);
    *(uint4*)&Wp[(size_t)i * 4] = o;
}

// ---------------------------------------------------------------------------
// TF32 GEMM, cp.async 2-stage, packed operands.
// CTA 128x128, 8 warps (4 M x 2 N), warp tile 32x64. K=1024, BK=32.
// MODE 1: epilogue scatters into g_Q/g_K/g_V (fp32, head-major), bias added.
// MODE 0: epilogue writes Cout + bias (fp32).
// Smem: 2 stages x (A 16KB + B 16KB) = 64KB dynamic.
// ---------------------------------------------------------------------------
#define GEMM_SMEM 65536

template <int MODE>
__global__ void __launch_bounds__(256, 2)
gemm_mma(const uint32_t* __restrict__ Apk, const uint32_t* __restrict__ Bpk,
         const float* __restrict__ bias, float* __restrict__ Cout)
{
    constexpr int NS = 32;
    extern __shared__ uint32_t sm[];     // [2][A 4096 | B 4096] u32
    const int tid  = threadIdx.x;
    const int wid  = tid >> 5;
    const int lane = tid & 31;
    const int g    = lane >> 2;
    const int tig  = lane & 3;
    const int m0   = blockIdx.y * 128;
    const int n0   = blockIdx.x * 128;
    const int mb0  = m0 >> 4;
    const int nb0  = n0 >> 3;
    const uint32_t smb = smem_u32(sm);

    float acc[2][8][4];
#pragma unroll
    for (int mf = 0; mf < 2; mf++)
#pragma unroll
        for (int nf = 0; nf < 8; nf++)
#pragma unroll
            for (int r = 0; r < 4; r++) acc[mf][nf][r] = 0.0f;

    // Per-thread copy map: 4 x 16B chunks per operand per slab.
    uint32_t asrc[4], bsrc[4], adst[4], bdst[4];
#pragma unroll
    for (int c = 0; c < 4; c++) {
        const int ci = c * 256 + tid;
        asrc[c] = (uint32_t)(mb0 + (ci >> 7)) * 16384u + (uint32_t)(ci & 127) * 4u;
        bsrc[c] = (uint32_t)(nb0 + (ci >> 6)) * 8192u  + (uint32_t)(ci & 63) * 4u;
        adst[c] = smb + (uint32_t)ci * 16u;
        bdst[c] = smb + 16384u + (uint32_t)ci * 16u;
    }

    auto issue = [&](int s, int buf) {
        const uint32_t so = (uint32_t)buf * 32768u;
#pragma unroll
        for (int c = 0; c < 4; c++)
            CP16(adst[c] + so, (const void*)(Apk + asrc[c] + (uint32_t)s * 512u));
#pragma unroll
        for (int c = 0; c < 4; c++)
            CP16(bdst[c] + so, (const void*)(Bpk + bsrc[c] + (uint32_t)s * 256u));
        CPCOMMIT();
    };

    issue(0, 0);

    const int wm4 = (wid & 3) * 2;       // A block base (in 16-row blocks)
    const int wn8 = (wid >> 2) * 8;      // B block base (in 8-col blocks)

    for (int s = 0; s < NS; s++) {
        if (s + 1 < NS) { issue(s + 1, (s + 1) & 1); CPWAIT1(); }
        else            { CPWAIT0(); }
        __syncthreads();

        const uint32_t* Ab = sm + (uint32_t)(s & 1) * 8192u;
        const uint32_t* Bb = Ab + 4096;

#pragma unroll
        for (int kp = 0; kp < 2; kp++) {
            uint4 af[2][2];
#pragma unroll
            for (int mf = 0; mf < 2; mf++)
#pragma unroll
                for (int h = 0; h < 2; h++)
                    af[mf][h] = *(const uint4*)&Ab[(((wm4 + mf) * 4 + kp * 2 + h) * 32 + lane) * 4];
#pragma unroll
            for (int nf = 0; nf < 8; nf++) {
                const uint4 bv = *(const uint4*)&Bb[(((wn8 + nf) * 2 + kp) * 32 + lane) * 4];
#pragma unroll
                for (int h = 0; h < 2; h++) {
                    uint32_t b2[2];
                    b2[0] = h ? bv.z : bv.x;
                    b2[1] = h ? bv.w : bv.y;
                    mma_tf32(acc[0][nf], (const uint32_t*)&af[0][h], b2);
                    mma_tf32(acc[1][nf], (const uint32_t*)&af[1][h], b2);
                }
            }
        }
        __syncthreads();
    }

    // Epilogue (same coordinates as before)
#pragma unroll
    for (int mf = 0; mf < 2; mf++) {
        const int row0 = m0 + (wid & 3) * 32 + mf * 16 + g;
#pragma unroll
        for (int nf = 0; nf < 8; nf++) {
            const int col = n0 + (wid >> 2) * 64 + nf * 8 + 2 * tig;
            const float2 bv = *(const float2*)(bias + col);
            float2 v0 = make_float2(acc[mf][nf][0] + bv.x, acc[mf][nf][1] + bv.y);
            float2 v1 = make_float2(acc[mf][nf][2] + bv.x, acc[mf][nf][3] + bv.y);
            if (MODE == 0) {
                *(float2*)(Cout + (size_t)row0 * D_MODEL + col)       = v0;
                *(float2*)(Cout + (size_t)(row0 + 8) * D_MODEL + col) = v1;
            } else {
                const int which = col >> 10;       // 0=Q 1=K 2=V
                const int c2    = col & 1023;
                const int h     = c2 >> 6;
                const int d     = c2 & 63;
                float* dst = (which == 0) ? g_Q : (which == 1) ? g_K : g_V;
                const int bb0 = row0 >> 11, t0 = row0 & 2047;
                const int r1  = row0 + 8;
                const int bb1 = r1 >> 11,   t1 = r1 & 2047;
                *(float2*)(dst + (((size_t)(bb0 * N_HEADS + h)) * SEQ + t0) * HD + d) = v0;
                *(float2*)(dst + (((size_t)(bb1 * N_HEADS + h)) * SEQ + t1) * HD + d) = v1;
            }
        }
    }
}

// ---------------------------------------------------------------------------
// Flash attention (Round-7 mainloop, unchanged). Epilogue now writes g_Yp in
// packed tf32 A-fragment layout via the same quad-shuffle transform as PV.
// ---------------------------------------------------------------------------
#define LDF 68
#define KPB 132
#define PACK_U32 (32 * KPB)
#define QROWS 256
#define FLASH_SMEM ((QROWS * LDF + 2 * PACK_U32) * 4)

__global__ void __launch_bounds__(256, 1)
flash_mma()
{
    extern __shared__ uint32_t fsm[];
    uint32_t* Qs = fsm;
    uint32_t* Kp = Qs + QROWS * LDF;
    uint32_t* Vp = Kp + PACK_U32;

    const int tid  = threadIdx.x;
    const int wid  = tid >> 5;
    const int lane = tid & 31;
    const int g    = lane >> 2;
    const int tig  = lane & 3;
    const int qt   = (int)gridDim.x - 1 - (int)blockIdx.x;
    const int bh   = blockIdx.y;
    const int q0   = qt * QROWS;

    const float QSCALE = 0.125f * 1.44269504f;

    {
        const int row = tid;
        const float* src = g_Q + ((size_t)bh * SEQ + q0 + row) * HD;
#pragma unroll
        for (int i = 0; i < 16; i++) {
            float4 v = *(const float4*)(src + i * 4);
            uint4 t = make_uint4(f2tf32(v.x * QSCALE), f2tf32(v.y * QSCALE),
                                 f2tf32(v.z * QSCALE), f2tf32(v.w * QSCALE));
            *(uint4*)&Qs[row * LDF + i * 4] = t;
        }
    }

    float mrow[2][2], lrow[2][2], Of[2][8][4];
#pragma unroll
    for (int mf = 0; mf < 2; mf++) {
        mrow[mf][0] = mrow[mf][1] = -1e30f;
        lrow[mf][0] = lrow[mf][1] = 0.0f;
#pragma unroll
        for (int nf = 0; nf < 8; nf++)
#pragma unroll
            for (int r = 0; r < 4; r++) Of[mf][nf][r] = 0.0f;
    }

    const int nt = qt * 4 + 4;

    const int skey = tid >> 2;
    const int skp  = tid & 3;
    const int sg   = skey & 7;
    const int snf  = skey >> 3;
    const int kstore = (snf * 4 + skp) * KPB + sg * 16;
    const int vkp  = skey >> 4;
    const int vt   = skey & 3;
    const int vslot = (skey >> 2) & 3;

    const float* kbase = g_K + (size_t)bh * SEQ * HD + (size_t)skey * HD + skp * 16;
    const float* vbase = g_V + (size_t)bh * SEQ * HD + (size_t)skey * HD + skp * 16;

    float4 pk[4], pv[4];
#pragma unroll
    for (int i = 0; i < 4; i++) {
        pk[i] = *(const float4*)(kbase + i * 4);
        pv[i] = *(const float4*)(vbase + i * 4);
    }

    for (int kt = 0; kt < nt; kt++) {
#pragma unroll
        for (int i = 0; i < 4; i++) {
            Kp[kstore + 0  + i] = f2tf32(pk[i].x);
            Kp[kstore + 4  + i] = f2tf32(pk[i].y);
            Kp[kstore + 8  + i] = f2tf32(pk[i].z);
            Kp[kstore + 12 + i] = f2tf32(pk[i].w);
        }
        {
            const int d0 = skp * 16;
#pragma unroll
            for (int i = 0; i < 4; i++) {
                const float vv[4] = {pv[i].x, pv[i].y, pv[i].z, pv[i].w};
#pragma unroll
                for (int w = 0; w < 4; w++) {
                    const int d = d0 + i * 4 + w;
                    Vp[((d >> 3) * 4 + vkp) * KPB + ((d & 7) * 4 + vt) * 4 + vslot]
                        = f2tf32(vv[w]);
                }
            }
        }
        __syncthreads();

        if (kt + 1 < nt) {
            const size_t off = (size_t)(kt + 1) * 64 * HD;
#pragma unroll
            for (int i = 0; i < 4; i++) {
                pk[i] = *(const float4*)(kbase + off + i * 4);
                pv[i] = *(const float4*)(vbase + off + i * 4);
            }
        }

        float sacc[2][8][4];
#pragma unroll
        for (int mf = 0; mf < 2; mf++)
#pragma unroll
            for (int nf = 0; nf < 8; nf++)
#pragma unroll
                for (int r = 0; r < 4; r++) sacc[mf][nf][r] = 0.0f;

#pragma unroll
        for (int kp = 0; kp < 4; kp++) {
            uint32_t aq[2][2][4];
#pragma unroll
            for (int mf = 0; mf < 2; mf++) {
                const int r0i = wid * 32 + mf * 16 + g;
#pragma unroll
                for (int h = 0; h < 2; h++) {
                    const int kb8 = (kp * 2 + h) * 8;
                    aq[mf][h][0] = Qs[r0i * LDF + kb8 + tig];
                    aq[mf][h][1] = Qs[(r0i + 8) * LDF + kb8 + tig];
                    aq[mf][h][2] = Qs[r0i * LDF + kb8 + tig + 4];
                    aq[mf][h][3] = Qs[(r0i + 8) * LDF + kb8 + tig + 4];
                }
            }
#pragma unroll
            for (int half = 0; half < 2; half++) {
                uint4 kb[4];
#pragma unroll
                for (int i = 0; i < 4; i++)
                    kb[i] = *(const uint4*)&Kp[((half * 4 + i) * 4 + kp) * KPB + lane * 4];
#pragma unroll
                for (int h = 0; h < 2; h++)
#pragma unroll
                    for (int i = 0; i < 4; i++) {
                        uint32_t b[2];
                        b[0] = h ? kb[i].z : kb[i].x;
                        b[1] = h ? kb[i].w : kb[i].y;
                        mma_tf32(sacc[0][half * 4 + i], aq[0][h], b);
                        mma_tf32(sacc[1][half * 4 + i], aq[1][h], b);
                    }
            }
        }

        if (kt >= nt - 4) {
            const int n0 = kt * 64;
#pragma unroll
            for (int mf = 0; mf < 2; mf++) {
                const int r0g = q0 + wid * 32 + mf * 16 + g;
#pragma unroll
                for (int nf = 0; nf < 8; nf++) {
                    const int c0 = n0 + nf * 8 + 2 * tig;
                    if (c0     > r0g)     sacc[mf][nf][0] = -1e30f;
                    if (c0 + 1 > r0g)     sacc[mf][nf][1] = -1e30f;
                    if (c0     > r0g + 8) sacc[mf][nf][2] = -1e30f;
                    if (c0 + 1 > r0g + 8) sacc[mf][nf][3] = -1e30f;
                }
            }
        }

        uint32_t P0[2][8], P1[2][8], P2[2][8], P3[2][8];
#pragma unroll
        for (int mf = 0; mf < 2; mf++) {
            float rm0 = -1e30f, rm1 = -1e30f;
#pragma unroll
            for (int nf = 0; nf < 8; nf++) {
                rm0 = fmaxf(rm0, fmaxf(sacc[mf][nf][0], sacc[mf][nf][1]));
                rm1 = fmaxf(rm1, fmaxf(sacc[mf][nf][2], sacc[mf][nf][3]));
            }
            rm0 = fmaxf(rm0, __shfl_xor_sync(0xffffffffu, rm0, 1));
            rm0 = fmaxf(rm0, __shfl_xor_sync(0xffffffffu, rm0, 2));
            rm1 = fmaxf(rm1, __shfl_xor_sync(0xffffffffu, rm1, 1));
            rm1 = fmaxf(rm1, __shfl_xor_sync(0xffffffffu, rm1, 2));

            const float nm0 = fmaxf(mrow[mf][0], rm0);
            const float nm1 = fmaxf(mrow[mf][1], rm1);
            const float al0 = exp2f(mrow[mf][0] - nm0);
            const float al1 = exp2f(mrow[mf][1] - nm1);
            mrow[mf][0] = nm0; mrow[mf][1] = nm1;

            float rs0 = 0.0f, rs1 = 0.0f;
#pragma unroll
            for (int nf = 0; nf < 8; nf++) {
                const float p0 = exp2f(sacc[mf][nf][0] - nm0);
                const float p1 = exp2f(sacc[mf][nf][1] - nm0);
                const float p2 = exp2f(sacc[mf][nf][2] - nm1);
                const float p3 = exp2f(sacc[mf][nf][3] - nm1);
                rs0 += p0 + p1;
                rs1 += p2 + p3;
                P0[mf][nf] = f2tf32(p0); P1[mf][nf] = f2tf32(p1);
                P2[mf][nf] = f2tf32(p2); P3[mf][nf] = f2tf32(p3);
            }
            rs0 += __shfl_xor_sync(0xffffffffu, rs0, 1);
            rs0 += __shfl_xor_sync(0xffffffffu, rs0, 2);
            rs1 += __shfl_xor_sync(0xffffffffu, rs1, 1);
            rs1 += __shfl_xor_sync(0xffffffffu, rs1, 2);
            lrow[mf][0] = lrow[mf][0] * al0 + rs0;
            lrow[mf][1] = lrow[mf][1] * al1 + rs1;

#pragma unroll
            for (int nf = 0; nf < 8; nf++) {
                Of[mf][nf][0] *= al0; Of[mf][nf][1] *= al0;
                Of[mf][nf][2] *= al1; Of[mf][nf][3] *= al1;
            }
        }

        const int srcA = (lane & 28) | (tig >> 1);
        const int srcB = srcA + 2;
        const bool hi  = (tig & 1);
#pragma unroll
        for (int kp = 0; kp < 4; kp++) {
            uint32_t ap[2][2][4];
#pragma unroll
            for (int mf = 0; mf < 2; mf++)
#pragma unroll
                for (int h = 0; h < 2; h++) {
                    const int kc = kp * 2 + h;
                    uint32_t x0 = __shfl_sync(0xffffffffu, P0[mf][kc], srcA);
                    uint32_t x1 = __shfl_sync(0xffffffffu, P1[mf][kc], srcA);
                    uint32_t y0 = __shfl_sync(0xffffffffu, P2[mf][kc], srcA);
                    uint32_t y1 = __shfl_sync(0xffffffffu, P3[mf][kc], srcA);
                    uint32_t z0 = __shfl_sync(0xffffffffu, P0[mf][kc], srcB);
                    uint32_t z1 = __shfl_sync(0xffffffffu, P1[mf][kc], srcB);
                    uint32_t w0 = __shfl_sync(0xffffffffu, P2[mf][kc], srcB);
                    uint32_t w1 = __shfl_sync(0xffffffffu, P3[mf][kc], srcB);
                    ap[mf][h][0] = hi ? x1 : x0;
                    ap[mf][h][1] = hi ? y1 : y0;
                    ap[mf][h][2] = hi ? z1 : z0;
                    ap[mf][h][3] = hi ? w1 : w0;
                }
#pragma unroll
            for (int half = 0; half < 2; half++) {
                uint4 vb[4];
#pragma unroll
                for (int i = 0; i < 4; i++)
                    vb[i] = *(const uint4*)&Vp[((half * 4 + i) * 4 + kp) * KPB + lane * 4];
#pragma unroll
                for (int h = 0; h < 2; h++)
#pragma unroll
                    for (int i = 0; i < 4; i++) {
                        uint32_t b[2];
                        b[0] = h ? vb[i].z : vb[i].x;
                        b[1] = h ? vb[i].w : vb[i].y;
                        mma_tf32(Of[0][half * 4 + i], ap[0][h], b);
                        mma_tf32(Of[1][half * 4 + i], ap[1][h], b);
                    }
            }
        }
        __syncthreads();
    }

    // Epilogue: write packed tf32 A-fragment g_Yp (quad-shuffle transform).
    const int b = bh >> 4;
    const int h = bh & 15;
    const int srcA = (lane & 28) | (tig >> 1);
    const int srcB = srcA + 2;
    const bool hi  = (tig & 1);
#pragma unroll
    for (int mf = 0; mf < 2; mf++) {
        const float inv0 = 1.0f / lrow[mf][0];
        const float inv1 = 1.0f / lrow[mf][1];
        const int mb = (b * SEQ + q0 + wid * 32 + mf * 16) >> 4;
#pragma unroll
        for (int j = 0; j < 8; j++) {
            const float n0f = Of[mf][j][0] * inv0;
            const float n1f = Of[mf][j][1] * inv0;
            const float n2f = Of[mf][j][2] * inv1;
            const float n3f = Of[mf][j][3] * inv1;
            const float x0 = __shfl_sync(0xffffffffu, n0f, srcA);
            const float x1 = __shfl_sync(0xffffffffu, n1f, srcA);
            const float y0 = __shfl_sync(0xffffffffu, n2f, srcA);
            const float y1 = __shfl_sync(0xffffffffu, n3f, srcA);
            const float z0 = __shfl_sync(0xffffffffu, n0f, srcB);
            const float z1 = __shfl_sync(0xffffffffu, n1f, srcB);
            const float w0 = __shfl_sync(0xffffffffu, n2f, srcB);
            const float w1 = __shfl_sync(0xffffffffu, n3f, srcB);
            uint4 o;
            o.x = f2tf32(hi ? x1 : x0);
            o.y = f2tf32(hi ? y1 : y0);
            o.z = f2tf32(hi ? z1 : z0);
            o.w = f2tf32(hi ? w1 : w0);
            const int slab = 2 * h + (j >> 2);
            const int kc   = j & 3;
            *(uint4*)&g_Yp[(((size_t)mb * 32 + slab) * 4 + kc) * 128 + lane * 4] = o;
        }
    }
}

// ---------------------------------------------------------------------------
extern "C" void kernel_launch(void* const* d_in, const int* in_sizes, int n_in,
                              void* d_out, int out_size)
{
    const float* x      = (const float*)d_in[0];
    const float* W_attn = (const float*)d_in[1];
    const float* b_attn = (const float*)d_in[2];
    const float* W_proj = (const float*)d_in[3];
    const float* b_proj = (const float*)d_in[4];
    float* out = (float*)d_out;

    cudaFuncSetAttribute(gemm_mma<1>, cudaFuncAttributeMaxDynamicSharedMemorySize, GEMM_SMEM);
    cudaFuncSetAttribute(gemm_mma<0>, cudaFuncAttributeMaxDynamicSharedMemorySize, GEMM_SMEM);
    cudaFuncSetAttribute(flash_mma, cudaFuncAttributeMaxDynamicSharedMemorySize, FLASH_SMEM);

    uint32_t* xp;  cudaGetSymbolAddress((void**)&xp,  g_Xp);
    uint32_t* yp;  cudaGetSymbolAddress((void**)&yp,  g_Yp);
    uint32_t* wpa; cudaGetSymbolAddress((void**)&wpa, g_Wpa);
    uint32_t* wpp; cudaGetSymbolAddress((void**)&wpp, g_Wpp);

    // 0) Pack operands to fragment-layout tf32
    pack_a<<<(M_TOK * D_MODEL / 4) / 256, 256>>>(x, xp);
    pack_b<<<(3 * D_MODEL * D_MODEL / 4) / 256, 256>>>(W_attn, wpa, 3 * D_MODEL);
    pack_b<<<(D_MODEL * D_MODEL / 4) / 256, 256>>>(W_proj, wpp, D_MODEL);

    // 1) QKV projection -> g_Q/g_K/g_V
    {
        dim3 grid(3 * D_MODEL / 128, M_TOK / 128);  // (24, 64)
        gemm_mma<1><<<grid, 256, GEMM_SMEM>>>(xp, wpa, b_attn, nullptr);
    }
    // 2) Causal flash attention -> g_Yp (packed tf32)
    {
        dim3 grid(SEQ / QROWS, BH);  // (8, 64)
        flash_mma<<<grid, 256, FLASH_SMEM>>>();
    }
    // 3) Output projection -> d_out
    {
        dim3 grid(D_MODEL / 128, M_TOK / 128);  // (8, 64)
        gemm_mma<0><<<grid, 256, GEMM_SMEM>>>(yp, wpp, b_proj, out);
    }
}